// round 1
// baseline (speedup 1.0000x reference)
#include <cuda_runtime.h>
#include <math.h>

#define SEQ 2048
#define HIDDEN 4096
#define NH 32
#define NKV 8
#define HD 128
#define QD (NH*HD)     // 4096
#define KVD (NKV*HD)   // 1024

// Scratch (static device globals: allocation-guard-safe)
__device__ float g_q[SEQ*QD];
__device__ float g_k[SEQ*KVD];
__device__ float g_v[SEQ*KVD];
__device__ float g_ctx[SEQ*QD];

// ---------------------------------------------------------------------------
// C[m,n] = sum_k A[m*K+k] * B[n*K+k]   (y = x @ W^T with W row-major [N,K])
// 128x128 tile, BK=16, 256 threads, 8x8 per thread, fp32.
// ---------------------------------------------------------------------------
__global__ void __launch_bounds__(256) sgemm_nt(const float* __restrict__ A,
                                                const float* __restrict__ B,
                                                float* __restrict__ C,
                                                int M, int N, int K) {
    __shared__ float As[16][132];
    __shared__ float Bs[16][132];
    const int tid = threadIdx.x;
    const int tx = tid & 15, ty = tid >> 4;
    const int m0 = blockIdx.y * 128, n0 = blockIdx.x * 128;
    const int lk = tid & 15, lr = tid >> 4;

    float acc[8][8];
#pragma unroll
    for (int i = 0; i < 8; ++i)
#pragma unroll
        for (int j = 0; j < 8; ++j) acc[i][j] = 0.f;

    const float* Ap = A + (long)(m0 + lr) * K + lk;
    const float* Bp = B + (long)(n0 + lr) * K + lk;

    for (int k0 = 0; k0 < K; k0 += 16) {
#pragma unroll
        for (int p = 0; p < 8; ++p) {
            As[lk][lr + p * 16] = Ap[(long)(p * 16) * K + k0];
            Bs[lk][lr + p * 16] = Bp[(long)(p * 16) * K + k0];
        }
        __syncthreads();
#pragma unroll
        for (int k = 0; k < 16; ++k) {
            float4 a0 = *(const float4*)&As[k][ty * 8];
            float4 a1 = *(const float4*)&As[k][ty * 8 + 4];
            float4 b0 = *(const float4*)&Bs[k][tx * 8];
            float4 b1 = *(const float4*)&Bs[k][tx * 8 + 4];
            float a[8] = {a0.x, a0.y, a0.z, a0.w, a1.x, a1.y, a1.z, a1.w};
            float b[8] = {b0.x, b0.y, b0.z, b0.w, b1.x, b1.y, b1.z, b1.w};
#pragma unroll
            for (int i = 0; i < 8; ++i)
#pragma unroll
                for (int j = 0; j < 8; ++j) acc[i][j] += a[i] * b[j];
        }
        __syncthreads();
    }

#pragma unroll
    for (int i = 0; i < 8; ++i) {
        float* Cp = C + (long)(m0 + ty * 8 + i) * N + n0 + tx * 8;
        *(float4*)Cp       = make_float4(acc[i][0], acc[i][1], acc[i][2], acc[i][3]);
        *(float4*)(Cp + 4) = make_float4(acc[i][4], acc[i][5], acc[i][6], acc[i][7]);
    }
}

// ---------------------------------------------------------------------------
// Per-(token, head) RMSNorm over D=128 then RoPE. One block = one row of 128.
// blockIdx.y < NH -> Q head, else K head (index - NH).
// ---------------------------------------------------------------------------
__global__ void __launch_bounds__(128) norm_rope_kernel(float* __restrict__ gq,
                                                        float* __restrict__ gk,
                                                        const float* __restrict__ qw,
                                                        const float* __restrict__ kw) {
    const int s = blockIdx.x;
    const int hy = blockIdx.y;
    float* base;
    const float* w;
    if (hy < NH) { base = gq + (long)s * QD + hy * HD;        w = qw; }
    else         { base = gk + (long)s * KVD + (hy - NH) * HD; w = kw; }

    const int t = threadIdx.x;
    float x = base[t];
    float v = x * x;
#pragma unroll
    for (int off = 16; off; off >>= 1) v += __shfl_xor_sync(0xffffffffu, v, off);

    __shared__ float ws[4];
    __shared__ float xs[128];
    if ((t & 31) == 0) ws[t >> 5] = v;
    __syncthreads();
    float var = (ws[0] + ws[1] + ws[2] + ws[3]) * (1.0f / 128.0f);
    float xn = x * rsqrtf(var + 1e-6f) * w[t];
    xs[t] = xn;
    __syncthreads();

    const int half = t & 63;
    // inv_freq = 1e6^(-half/64) = 2^(-log2(1e6)*half/64)
    float invf = exp2f(-19.931568569324174f * ((float)half * (1.0f / 64.0f)));
    float ang = (float)s * invf;
    float c = cosf(ang), sn = sinf(ang);
    float rot = (t < 64) ? -xs[t + 64] : xs[t - 64];
    base[t] = xn * c + rot * sn;
}

// ---------------------------------------------------------------------------
// Flash attention (fp32 SIMT). One block: 64 queries x 1 head. 256 threads.
// Thread (tx,ty), tx=tid&15, ty=tid>>4: owns score rows ty*4+i, cols tx*4+j;
// output rows ty*4+i, cols tx*8+c. Online softmax state per row (replicated
// across the 16-lane tx-group via shfl reductions).
// smem: Qt[128][68] (K-major transposed), Kt[128][68], Vs[64][132], Pt[64][68]
// ---------------------------------------------------------------------------
#define QT_STRIDE 68
#define VS_STRIDE 132
#define ATTN_SMEM_FLOATS (128*QT_STRIDE + 128*QT_STRIDE + 64*VS_STRIDE + 64*QT_STRIDE)
#define ATTN_SMEM_BYTES (ATTN_SMEM_FLOATS * 4)

__global__ void __launch_bounds__(256) attn_kernel(const float* __restrict__ gq,
                                                   const float* __restrict__ gk,
                                                   const float* __restrict__ gv,
                                                   float* __restrict__ gctx) {
    extern __shared__ float sm[];
    float* Qt = sm;                        // [128][68]
    float* Kt = Qt + 128 * QT_STRIDE;      // [128][68]
    float* Vs = Kt + 128 * QT_STRIDE;      // [64][132]
    float* Pt = Vs + 64 * VS_STRIDE;       // [64][68]

    const int tid = threadIdx.x;
    const int tx = tid & 15, ty = tid >> 4;
    const int q0 = blockIdx.x << 6;
    const int h = blockIdx.y;
    const int kvh = h >> 2;                // GQA repeat factor 4
    const float scale = 0.08838834764831845f;  // 1/sqrt(128)

    // Load Q tile transposed: Qt[k][r]
    for (int idx = tid; idx < 64 * 128; idx += 256) {
        int r = idx >> 7, k = idx & 127;
        Qt[k * QT_STRIDE + r] = gq[(long)(q0 + r) * QD + h * HD + k];
    }

    float m_run[4], l_run[4];
    float acc[4][8];
#pragma unroll
    for (int i = 0; i < 4; ++i) {
        m_run[i] = -1e30f; l_run[i] = 0.f;
#pragma unroll
        for (int j = 0; j < 8; ++j) acc[i][j] = 0.f;
    }

    const int ntiles = blockIdx.x + 1;     // causal: key tiles 0..q0/64
    for (int t = 0; t < ntiles; ++t) {
        const int k0 = t << 6;
        __syncthreads();   // protect Kt/Vs/Pt from previous iteration readers
        for (int idx = tid; idx < 64 * 128; idx += 256) {
            int r = idx >> 7, k = idx & 127;
            long gidx = (long)(k0 + r) * KVD + kvh * HD + k;
            Kt[k * QT_STRIDE + r] = gk[gidx];
            Vs[r * VS_STRIDE + k] = gv[gidx];
        }
        __syncthreads();

        // S = Q K^T  (4x4 per thread)
        float s[4][4];
#pragma unroll
        for (int i = 0; i < 4; ++i)
#pragma unroll
            for (int j = 0; j < 4; ++j) s[i][j] = 0.f;
#pragma unroll 8
        for (int k = 0; k < 128; ++k) {
            float4 a = *(const float4*)&Qt[k * QT_STRIDE + ty * 4];
            float4 b = *(const float4*)&Kt[k * QT_STRIDE + tx * 4];
            float av[4] = {a.x, a.y, a.z, a.w};
            float bv[4] = {b.x, b.y, b.z, b.w};
#pragma unroll
            for (int i = 0; i < 4; ++i)
#pragma unroll
                for (int j = 0; j < 4; ++j) s[i][j] += av[i] * bv[j];
        }

        const bool diag = (t == ntiles - 1);
#pragma unroll
        for (int i = 0; i < 4; ++i) {
            float rowm = -1e30f;
#pragma unroll
            for (int j = 0; j < 4; ++j) {
                float v = s[i][j] * scale;
                if (diag && (tx * 4 + j > ty * 4 + i)) v = -1e30f;
                s[i][j] = v;
                rowm = fmaxf(rowm, v);
            }
#pragma unroll
            for (int off = 1; off < 16; off <<= 1)
                rowm = fmaxf(rowm, __shfl_xor_sync(0xffffffffu, rowm, off));
            float m_new = fmaxf(m_run[i], rowm);
            float corr = __expf(m_run[i] - m_new);
            float rsum = 0.f;
#pragma unroll
            for (int j = 0; j < 4; ++j) {
                float p = __expf(s[i][j] - m_new);
                s[i][j] = p;
                rsum += p;
            }
#pragma unroll
            for (int off = 1; off < 16; off <<= 1)
                rsum += __shfl_xor_sync(0xffffffffu, rsum, off);
            l_run[i] = l_run[i] * corr + rsum;
            m_run[i] = m_new;
#pragma unroll
            for (int j = 0; j < 8; ++j) acc[i][j] *= corr;
        }

        // Store P transposed: Pt[j][r]
#pragma unroll
        for (int j = 0; j < 4; ++j)
#pragma unroll
            for (int i = 0; i < 4; ++i)
                Pt[(tx * 4 + j) * QT_STRIDE + ty * 4 + i] = s[i][j];
        __syncthreads();

        // O += P V  (4 rows x 8 cols per thread)
#pragma unroll 4
        for (int j = 0; j < 64; ++j) {
            float4 p4 = *(const float4*)&Pt[j * QT_STRIDE + ty * 4];
            float4 v0 = *(const float4*)&Vs[j * VS_STRIDE + tx * 8];
            float4 v1 = *(const float4*)&Vs[j * VS_STRIDE + tx * 8 + 4];
            float pv[4] = {p4.x, p4.y, p4.z, p4.w};
            float vv[8] = {v0.x, v0.y, v0.z, v0.w, v1.x, v1.y, v1.z, v1.w};
#pragma unroll
            for (int i = 0; i < 4; ++i)
#pragma unroll
                for (int c = 0; c < 8; ++c) acc[i][c] += pv[i] * vv[c];
        }
    }

    // Epilogue: normalize by l, write to ctx [s, h*128 + d]
#pragma unroll
    for (int i = 0; i < 4; ++i) {
        float inv = 1.f / l_run[i];
        float* op = gctx + (long)(q0 + ty * 4 + i) * QD + h * HD + tx * 8;
        *(float4*)op       = make_float4(acc[i][0] * inv, acc[i][1] * inv,
                                         acc[i][2] * inv, acc[i][3] * inv);
        *(float4*)(op + 4) = make_float4(acc[i][4] * inv, acc[i][5] * inv,
                                         acc[i][6] * inv, acc[i][7] * inv);
    }
}

// ---------------------------------------------------------------------------
extern "C" void kernel_launch(void* const* d_in, const int* in_sizes, int n_in,
                              void* d_out, int out_size) {
    // metadata order: hidden_states, attention_mask, position_ids, Wq, Wk, Wv,
    //                 Wo, q_norm_w, k_norm_w
    const float* hidden = (const float*)d_in[0];
    // d_in[1] causal mask, d_in[2] position_ids: deterministic (tril / arange),
    // computed analytically in-kernel.
    const float* Wq = (const float*)d_in[3];
    const float* Wk = (const float*)d_in[4];
    const float* Wv = (const float*)d_in[5];
    const float* Wo = (const float*)d_in[6];
    const float* qw = (const float*)d_in[7];
    const float* kw = (const float*)d_in[8];
    float* out = (float*)d_out;

    float *pq, *pk, *pv, *pctx;
    cudaGetSymbolAddress((void**)&pq, g_q);
    cudaGetSymbolAddress((void**)&pk, g_k);
    cudaGetSymbolAddress((void**)&pv, g_v);
    cudaGetSymbolAddress((void**)&pctx, g_ctx);

    // QKV projections
    sgemm_nt<<<dim3(QD / 128, SEQ / 128), 256>>>(hidden, Wq, pq, SEQ, QD, HIDDEN);
    sgemm_nt<<<dim3(KVD / 128, SEQ / 128), 256>>>(hidden, Wk, pk, SEQ, KVD, HIDDEN);
    sgemm_nt<<<dim3(KVD / 128, SEQ / 128), 256>>>(hidden, Wv, pv, SEQ, KVD, HIDDEN);

    // RMSNorm + RoPE on Q and K
    norm_rope_kernel<<<dim3(SEQ, NH + NKV), 128>>>(pq, pk, qw, kw);

    // Flash attention
    cudaFuncSetAttribute(attn_kernel, cudaFuncAttributeMaxDynamicSharedMemorySize,
                         ATTN_SMEM_BYTES);
    attn_kernel<<<dim3(SEQ / 64, NH), 256, ATTN_SMEM_BYTES>>>(pq, pk, pv, pctx);

    // Output projection -> d_out
    sgemm_nt<<<dim3(HIDDEN / 128, SEQ / 128), 256>>>(pctx, Wo, out, SEQ, HIDDEN, HIDDEN);
}

// round 2
// speedup vs baseline: 2.2225x; 2.2225x over previous
#include <cuda_runtime.h>
#include <math.h>
#include <stdint.h>

#define SEQ 2048
#define HIDDEN 4096
#define NH 32
#define NKV 8
#define HD 128
#define QD (NH*HD)     // 4096
#define KVD (NKV*HD)   // 1024

// Scratch (static device globals: allocation-guard-safe)
__device__ float g_q[SEQ*QD];
__device__ float g_k[SEQ*KVD];
__device__ float g_v[SEQ*KVD];
__device__ float g_ctx[SEQ*QD];
// tf32-rounded copies (RNA rounding; avoids biased truncation in HMMA)
__device__ float g_hid_t[SEQ*HIDDEN];
__device__ float g_wq_t[QD*HIDDEN];
__device__ float g_wk_t[KVD*HIDDEN];
__device__ float g_wv_t[KVD*HIDDEN];
__device__ float g_wo_t[HIDDEN*QD];

__device__ __forceinline__ float tf32_rna(float x) {
    uint32_t u;
    asm("cvt.rna.tf32.f32 %0, %1;" : "=r"(u) : "f"(x));
    return __uint_as_float(u);
}

// ---------------------------------------------------------------------------
// Round fp32 -> tf32 (RNA). n multiple of 1024.
// ---------------------------------------------------------------------------
__global__ void __launch_bounds__(256) round_tf32_kernel(float* __restrict__ dst,
                                                         const float* __restrict__ src) {
    int i = (blockIdx.x * 256 + threadIdx.x) * 4;
    float4 v = *(const float4*)(src + i);
    v.x = tf32_rna(v.x); v.y = tf32_rna(v.y);
    v.z = tf32_rna(v.z); v.w = tf32_rna(v.w);
    *(float4*)(dst + i) = v;
}

// ---------------------------------------------------------------------------
// tf32 tensor-core GEMM: C[m,n] = sum_k A[m*K+k]*B[n*K+k]  (y = x @ W^T)
// 128x128 tile, BK=32, 256 threads (8 warps: 4(m) x 2(n), warp tile 32x64),
// mma.sync.m16n8k8.tf32, cp.async double-buffered.
// Requires M%128==0, N%128==0, K%32==0.
// ---------------------------------------------------------------------------
#define GS_STRIDE 36                    // smem row stride (floats)
#define GS_TILE   (128*GS_STRIDE)      // one A or B tile
#define GS_STAGE  (2*GS_TILE)          // A+B per stage
#define GEMM_SMEM_BYTES (2*GS_STAGE*4) // 2 stages

__global__ void __launch_bounds__(256) sgemm_tf32(const float* __restrict__ A,
                                                  const float* __restrict__ B,
                                                  float* __restrict__ C,
                                                  int M, int N, int K) {
    extern __shared__ float smem[];
    const int tid = threadIdx.x;
    const int lane = tid & 31;
    const int warp = tid >> 5;
    const int wm = (warp & 3) * 32;
    const int wn = (warp >> 2) * 64;
    const int m0 = blockIdx.y * 128, n0 = blockIdx.x * 128;

    float acc[2][8][4];
#pragma unroll
    for (int i = 0; i < 2; ++i)
#pragma unroll
        for (int j = 0; j < 8; ++j)
#pragma unroll
            for (int r = 0; r < 4; ++r) acc[i][j][r] = 0.f;

    const int nk = K >> 5;

    // --- prefetch stage s for k-block k0 ---
    auto prefetch = [&](int s, int k0) {
        float* as = smem + s * GS_STAGE;
        float* bs = as + GS_TILE;
#pragma unroll
        for (int i = 0; i < 4; ++i) {
            int c = tid + i * 256;              // 0..1023
            int row = c >> 3, col = (c & 7) << 2;
            uint32_t ad = (uint32_t)__cvta_generic_to_shared(as + row * GS_STRIDE + col);
            const float* ga = A + (long)(m0 + row) * K + k0 + col;
            asm volatile("cp.async.cg.shared.global [%0], [%1], 16;\n" :: "r"(ad), "l"(ga));
            uint32_t bd = (uint32_t)__cvta_generic_to_shared(bs + row * GS_STRIDE + col);
            const float* gb = B + (long)(n0 + row) * K + k0 + col;
            asm volatile("cp.async.cg.shared.global [%0], [%1], 16;\n" :: "r"(bd), "l"(gb));
        }
        asm volatile("cp.async.commit_group;\n");
    };

    prefetch(0, 0);

    for (int t = 0; t < nk; ++t) {
        if (t + 1 < nk) {
            prefetch((t + 1) & 1, (t + 1) << 5);
            asm volatile("cp.async.wait_group 1;\n");
        } else {
            asm volatile("cp.async.wait_group 0;\n");
        }
        __syncthreads();

        const float* as = smem + (t & 1) * GS_STAGE;
        const float* bs = as + GS_TILE;
        const int r = lane >> 2, c4 = lane & 3;

#pragma unroll
        for (int kk = 0; kk < 32; kk += 8) {
            uint32_t a[2][4];
#pragma unroll
            for (int i = 0; i < 2; ++i) {
                const float* ap = as + (wm + i * 16 + r) * GS_STRIDE + kk + c4;
                a[i][0] = __float_as_uint(ap[0]);
                a[i][1] = __float_as_uint(ap[8 * GS_STRIDE]);
                a[i][2] = __float_as_uint(ap[4]);
                a[i][3] = __float_as_uint(ap[8 * GS_STRIDE + 4]);
            }
            uint32_t b[8][2];
#pragma unroll
            for (int j = 0; j < 8; ++j) {
                const float* bp = bs + (wn + j * 8 + r) * GS_STRIDE + kk + c4;
                b[j][0] = __float_as_uint(bp[0]);
                b[j][1] = __float_as_uint(bp[4]);
            }
#pragma unroll
            for (int i = 0; i < 2; ++i)
#pragma unroll
                for (int j = 0; j < 8; ++j) {
                    float* d = acc[i][j];
                    asm volatile(
                        "mma.sync.aligned.m16n8k8.row.col.f32.tf32.tf32.f32 "
                        "{%0,%1,%2,%3},{%4,%5,%6,%7},{%8,%9},{%0,%1,%2,%3};\n"
                        : "+f"(d[0]), "+f"(d[1]), "+f"(d[2]), "+f"(d[3])
                        : "r"(a[i][0]), "r"(a[i][1]), "r"(a[i][2]), "r"(a[i][3]),
                          "r"(b[j][0]), "r"(b[j][1]));
                }
        }
        __syncthreads();
    }

    // epilogue
    const int r = lane >> 2, c2 = (lane & 3) * 2;
#pragma unroll
    for (int i = 0; i < 2; ++i)
#pragma unroll
        for (int j = 0; j < 8; ++j) {
            long row0 = m0 + wm + i * 16 + r;
            long col = n0 + wn + j * 8 + c2;
            *(float2*)&C[row0 * N + col]       = make_float2(acc[i][j][0], acc[i][j][1]);
            *(float2*)&C[(row0 + 8) * N + col] = make_float2(acc[i][j][2], acc[i][j][3]);
        }
}

// ---------------------------------------------------------------------------
// Per-(token, head) RMSNorm over D=128 then RoPE. One block = one row of 128.
// ---------------------------------------------------------------------------
__global__ void __launch_bounds__(128) norm_rope_kernel(float* __restrict__ gq,
                                                        float* __restrict__ gk,
                                                        const float* __restrict__ qw,
                                                        const float* __restrict__ kw) {
    const int s = blockIdx.x;
    const int hy = blockIdx.y;
    float* base;
    const float* w;
    if (hy < NH) { base = gq + (long)s * QD + hy * HD;        w = qw; }
    else         { base = gk + (long)s * KVD + (hy - NH) * HD; w = kw; }

    const int t = threadIdx.x;
    float x = base[t];
    float v = x * x;
#pragma unroll
    for (int off = 16; off; off >>= 1) v += __shfl_xor_sync(0xffffffffu, v, off);

    __shared__ float ws[4];
    __shared__ float xs[128];
    if ((t & 31) == 0) ws[t >> 5] = v;
    __syncthreads();
    float var = (ws[0] + ws[1] + ws[2] + ws[3]) * (1.0f / 128.0f);
    float xn = x * rsqrtf(var + 1e-6f) * w[t];
    xs[t] = xn;
    __syncthreads();

    const int half = t & 63;
    float invf = exp2f(-19.931568569324174f * ((float)half * (1.0f / 64.0f)));
    float ang = (float)s * invf;
    float c = cosf(ang), sn = sinf(ang);
    float rot = (t < 64) ? -xs[t + 64] : xs[t - 64];
    base[t] = xn * c + rot * sn;
}

// ---------------------------------------------------------------------------
// Flash attention (fp32 SIMT), unchanged from R1 except tf32-rounded output
// so the O-projection tensor-core GEMM consumes pre-rounded data.
// ---------------------------------------------------------------------------
#define QT_STRIDE 68
#define VS_STRIDE 132
#define ATTN_SMEM_FLOATS (128*QT_STRIDE + 128*QT_STRIDE + 64*VS_STRIDE + 64*QT_STRIDE)
#define ATTN_SMEM_BYTES (ATTN_SMEM_FLOATS * 4)

__global__ void __launch_bounds__(256) attn_kernel(const float* __restrict__ gq,
                                                   const float* __restrict__ gk,
                                                   const float* __restrict__ gv,
                                                   float* __restrict__ gctx) {
    extern __shared__ float sm[];
    float* Qt = sm;
    float* Kt = Qt + 128 * QT_STRIDE;
    float* Vs = Kt + 128 * QT_STRIDE;
    float* Pt = Vs + 64 * VS_STRIDE;

    const int tid = threadIdx.x;
    const int tx = tid & 15, ty = tid >> 4;
    const int q0 = blockIdx.x << 6;
    const int h = blockIdx.y;
    const int kvh = h >> 2;
    const float scale = 0.08838834764831845f;

    for (int idx = tid; idx < 64 * 128; idx += 256) {
        int r = idx >> 7, k = idx & 127;
        Qt[k * QT_STRIDE + r] = gq[(long)(q0 + r) * QD + h * HD + k];
    }

    float m_run[4], l_run[4];
    float acc[4][8];
#pragma unroll
    for (int i = 0; i < 4; ++i) {
        m_run[i] = -1e30f; l_run[i] = 0.f;
#pragma unroll
        for (int j = 0; j < 8; ++j) acc[i][j] = 0.f;
    }

    const int ntiles = blockIdx.x + 1;
    for (int t = 0; t < ntiles; ++t) {
        const int k0 = t << 6;
        __syncthreads();
        for (int idx = tid; idx < 64 * 128; idx += 256) {
            int r = idx >> 7, k = idx & 127;
            long gidx = (long)(k0 + r) * KVD + kvh * HD + k;
            Kt[k * QT_STRIDE + r] = gk[gidx];
            Vs[r * VS_STRIDE + k] = gv[gidx];
        }
        __syncthreads();

        float s[4][4];
#pragma unroll
        for (int i = 0; i < 4; ++i)
#pragma unroll
            for (int j = 0; j < 4; ++j) s[i][j] = 0.f;
#pragma unroll 8
        for (int k = 0; k < 128; ++k) {
            float4 a = *(const float4*)&Qt[k * QT_STRIDE + ty * 4];
            float4 b = *(const float4*)&Kt[k * QT_STRIDE + tx * 4];
            float av[4] = {a.x, a.y, a.z, a.w};
            float bv[4] = {b.x, b.y, b.z, b.w};
#pragma unroll
            for (int i = 0; i < 4; ++i)
#pragma unroll
                for (int j = 0; j < 4; ++j) s[i][j] += av[i] * bv[j];
        }

        const bool diag = (t == ntiles - 1);
#pragma unroll
        for (int i = 0; i < 4; ++i) {
            float rowm = -1e30f;
#pragma unroll
            for (int j = 0; j < 4; ++j) {
                float v = s[i][j] * scale;
                if (diag && (tx * 4 + j > ty * 4 + i)) v = -1e30f;
                s[i][j] = v;
                rowm = fmaxf(rowm, v);
            }
#pragma unroll
            for (int off = 1; off < 16; off <<= 1)
                rowm = fmaxf(rowm, __shfl_xor_sync(0xffffffffu, rowm, off));
            float m_new = fmaxf(m_run[i], rowm);
            float corr = __expf(m_run[i] - m_new);
            float rsum = 0.f;
#pragma unroll
            for (int j = 0; j < 4; ++j) {
                float p = __expf(s[i][j] - m_new);
                s[i][j] = p;
                rsum += p;
            }
#pragma unroll
            for (int off = 1; off < 16; off <<= 1)
                rsum += __shfl_xor_sync(0xffffffffu, rsum, off);
            l_run[i] = l_run[i] * corr + rsum;
            m_run[i] = m_new;
#pragma unroll
            for (int j = 0; j < 8; ++j) acc[i][j] *= corr;
        }

#pragma unroll
        for (int j = 0; j < 4; ++j)
#pragma unroll
            for (int i = 0; i < 4; ++i)
                Pt[(tx * 4 + j) * QT_STRIDE + ty * 4 + i] = s[i][j];
        __syncthreads();

#pragma unroll 4
        for (int j = 0; j < 64; ++j) {
            float4 p4 = *(const float4*)&Pt[j * QT_STRIDE + ty * 4];
            float4 v0 = *(const float4*)&Vs[j * VS_STRIDE + tx * 8];
            float4 v1 = *(const float4*)&Vs[j * VS_STRIDE + tx * 8 + 4];
            float pv[4] = {p4.x, p4.y, p4.z, p4.w};
            float vv[8] = {v0.x, v0.y, v0.z, v0.w, v1.x, v1.y, v1.z, v1.w};
#pragma unroll
            for (int i = 0; i < 4; ++i)
#pragma unroll
                for (int c = 0; c < 8; ++c) acc[i][c] += pv[i] * vv[c];
        }
    }

#pragma unroll
    for (int i = 0; i < 4; ++i) {
        float inv = 1.f / l_run[i];
        float* op = gctx + (long)(q0 + ty * 4 + i) * QD + h * HD + tx * 8;
        *(float4*)op       = make_float4(tf32_rna(acc[i][0] * inv), tf32_rna(acc[i][1] * inv),
                                         tf32_rna(acc[i][2] * inv), tf32_rna(acc[i][3] * inv));
        *(float4*)(op + 4) = make_float4(tf32_rna(acc[i][4] * inv), tf32_rna(acc[i][5] * inv),
                                         tf32_rna(acc[i][6] * inv), tf32_rna(acc[i][7] * inv));
    }
}

// ---------------------------------------------------------------------------
extern "C" void kernel_launch(void* const* d_in, const int* in_sizes, int n_in,
                              void* d_out, int out_size) {
    const float* hidden = (const float*)d_in[0];
    const float* Wq = (const float*)d_in[3];
    const float* Wk = (const float*)d_in[4];
    const float* Wv = (const float*)d_in[5];
    const float* Wo = (const float*)d_in[6];
    const float* qw = (const float*)d_in[7];
    const float* kw = (const float*)d_in[8];
    float* out = (float*)d_out;

    float *pq, *pk, *pv, *pctx, *phid, *pwq, *pwk, *pwv, *pwo;
    cudaGetSymbolAddress((void**)&pq, g_q);
    cudaGetSymbolAddress((void**)&pk, g_k);
    cudaGetSymbolAddress((void**)&pv, g_v);
    cudaGetSymbolAddress((void**)&pctx, g_ctx);
    cudaGetSymbolAddress((void**)&phid, g_hid_t);
    cudaGetSymbolAddress((void**)&pwq, g_wq_t);
    cudaGetSymbolAddress((void**)&pwk, g_wk_t);
    cudaGetSymbolAddress((void**)&pwv, g_wv_t);
    cudaGetSymbolAddress((void**)&pwo, g_wo_t);

    // tf32 RNA pre-rounding
    round_tf32_kernel<<<(SEQ*HIDDEN)/1024, 256>>>(phid, hidden);
    round_tf32_kernel<<<(QD*HIDDEN)/1024, 256>>>(pwq, Wq);
    round_tf32_kernel<<<(KVD*HIDDEN)/1024, 256>>>(pwk, Wk);
    round_tf32_kernel<<<(KVD*HIDDEN)/1024, 256>>>(pwv, Wv);
    round_tf32_kernel<<<(HIDDEN*QD)/1024, 256>>>(pwo, Wo);

    cudaFuncSetAttribute(sgemm_tf32, cudaFuncAttributeMaxDynamicSharedMemorySize,
                         GEMM_SMEM_BYTES);

    // QKV projections (tensor cores)
    sgemm_tf32<<<dim3(QD / 128, SEQ / 128), 256, GEMM_SMEM_BYTES>>>(phid, pwq, pq, SEQ, QD, HIDDEN);
    sgemm_tf32<<<dim3(KVD / 128, SEQ / 128), 256, GEMM_SMEM_BYTES>>>(phid, pwk, pk, SEQ, KVD, HIDDEN);
    sgemm_tf32<<<dim3(KVD / 128, SEQ / 128), 256, GEMM_SMEM_BYTES>>>(phid, pwv, pv, SEQ, KVD, HIDDEN);

    // RMSNorm + RoPE on Q and K
    norm_rope_kernel<<<dim3(SEQ, NH + NKV), 128>>>(pq, pk, qw, kw);

    // Flash attention (fp32 SIMT)
    cudaFuncSetAttribute(attn_kernel, cudaFuncAttributeMaxDynamicSharedMemorySize,
                         ATTN_SMEM_BYTES);
    attn_kernel<<<dim3(SEQ / 64, NH), 256, ATTN_SMEM_BYTES>>>(pq, pk, pv, pctx);

    // Output projection -> d_out (tensor cores)
    sgemm_tf32<<<dim3(HIDDEN / 128, SEQ / 128), 256, GEMM_SMEM_BYTES>>>(pctx, pwo, out, SEQ, HIDDEN, HIDDEN);
}

// round 3
// speedup vs baseline: 3.3160x; 1.4920x over previous
#include <cuda_runtime.h>
#include <math.h>
#include <stdint.h>

#define SEQ 2048
#define HIDDEN 4096
#define NH 32
#define NKV 8
#define HD 128
#define QD (NH*HD)     // 4096
#define KVD (NKV*HD)   // 1024

// Scratch (static device globals: allocation-guard-safe)
__device__ float g_q[SEQ*QD];
__device__ float g_k[SEQ*KVD];
__device__ float g_v[SEQ*KVD];
__device__ float g_ctx[SEQ*QD];
__device__ float g_hid_t[SEQ*HIDDEN];
__device__ float g_wq_t[QD*HIDDEN];
__device__ float g_wk_t[KVD*HIDDEN];
__device__ float g_wv_t[KVD*HIDDEN];
__device__ float g_wo_t[HIDDEN*QD];

__device__ __forceinline__ float tf32_rna(float x) {
    uint32_t u;
    asm("cvt.rna.tf32.f32 %0, %1;" : "=r"(u) : "f"(x));
    return __uint_as_float(u);
}

__device__ __forceinline__ void mma_tf32(float* d, const uint32_t* a,
                                         uint32_t b0, uint32_t b1) {
    asm volatile(
        "mma.sync.aligned.m16n8k8.row.col.f32.tf32.tf32.f32 "
        "{%0,%1,%2,%3},{%4,%5,%6,%7},{%8,%9},{%0,%1,%2,%3};\n"
        : "+f"(d[0]), "+f"(d[1]), "+f"(d[2]), "+f"(d[3])
        : "r"(a[0]), "r"(a[1]), "r"(a[2]), "r"(a[3]), "r"(b0), "r"(b1));
}

// ---------------------------------------------------------------------------
__global__ void __launch_bounds__(256) round_tf32_kernel(float* __restrict__ dst,
                                                         const float* __restrict__ src) {
    int i = (blockIdx.x * 256 + threadIdx.x) * 4;
    float4 v = *(const float4*)(src + i);
    v.x = tf32_rna(v.x); v.y = tf32_rna(v.y);
    v.z = tf32_rna(v.z); v.w = tf32_rna(v.w);
    *(float4*)(dst + i) = v;
}

// ---------------------------------------------------------------------------
// tf32 tensor-core GEMM: C[m,n] = sum_k A[m*K+k]*B[n*K+k]  (y = x @ W^T)
// ---------------------------------------------------------------------------
#define GS_STRIDE 36
#define GS_TILE   (128*GS_STRIDE)
#define GS_STAGE  (2*GS_TILE)
#define GEMM_SMEM_BYTES (2*GS_STAGE*4)

__global__ void __launch_bounds__(256) sgemm_tf32(const float* __restrict__ A,
                                                  const float* __restrict__ B,
                                                  float* __restrict__ C,
                                                  int M, int N, int K) {
    extern __shared__ float smem[];
    const int tid = threadIdx.x;
    const int lane = tid & 31;
    const int warp = tid >> 5;
    const int wm = (warp & 3) * 32;
    const int wn = (warp >> 2) * 64;
    const int m0 = blockIdx.y * 128, n0 = blockIdx.x * 128;

    float acc[2][8][4];
#pragma unroll
    for (int i = 0; i < 2; ++i)
#pragma unroll
        for (int j = 0; j < 8; ++j)
#pragma unroll
            for (int r = 0; r < 4; ++r) acc[i][j][r] = 0.f;

    const int nk = K >> 5;

    auto prefetch = [&](int s, int k0) {
        float* as = smem + s * GS_STAGE;
        float* bs = as + GS_TILE;
#pragma unroll
        for (int i = 0; i < 4; ++i) {
            int c = tid + i * 256;
            int row = c >> 3, col = (c & 7) << 2;
            uint32_t ad = (uint32_t)__cvta_generic_to_shared(as + row * GS_STRIDE + col);
            const float* ga = A + (long)(m0 + row) * K + k0 + col;
            asm volatile("cp.async.cg.shared.global [%0], [%1], 16;\n" :: "r"(ad), "l"(ga));
            uint32_t bd = (uint32_t)__cvta_generic_to_shared(bs + row * GS_STRIDE + col);
            const float* gb = B + (long)(n0 + row) * K + k0 + col;
            asm volatile("cp.async.cg.shared.global [%0], [%1], 16;\n" :: "r"(bd), "l"(gb));
        }
        asm volatile("cp.async.commit_group;\n");
    };

    prefetch(0, 0);

    for (int t = 0; t < nk; ++t) {
        if (t + 1 < nk) {
            prefetch((t + 1) & 1, (t + 1) << 5);
            asm volatile("cp.async.wait_group 1;\n");
        } else {
            asm volatile("cp.async.wait_group 0;\n");
        }
        __syncthreads();

        const float* as = smem + (t & 1) * GS_STAGE;
        const float* bs = as + GS_TILE;
        const int r = lane >> 2, c4 = lane & 3;

#pragma unroll
        for (int kk = 0; kk < 32; kk += 8) {
            uint32_t a[2][4];
#pragma unroll
            for (int i = 0; i < 2; ++i) {
                const float* ap = as + (wm + i * 16 + r) * GS_STRIDE + kk + c4;
                a[i][0] = __float_as_uint(ap[0]);
                a[i][1] = __float_as_uint(ap[8 * GS_STRIDE]);
                a[i][2] = __float_as_uint(ap[4]);
                a[i][3] = __float_as_uint(ap[8 * GS_STRIDE + 4]);
            }
            uint32_t b[8][2];
#pragma unroll
            for (int j = 0; j < 8; ++j) {
                const float* bp = bs + (wn + j * 8 + r) * GS_STRIDE + kk + c4;
                b[j][0] = __float_as_uint(bp[0]);
                b[j][1] = __float_as_uint(bp[4]);
            }
#pragma unroll
            for (int i = 0; i < 2; ++i)
#pragma unroll
                for (int j = 0; j < 8; ++j)
                    mma_tf32(acc[i][j], a[i], b[j][0], b[j][1]);
        }
        __syncthreads();
    }

    const int r = lane >> 2, c2 = (lane & 3) * 2;
#pragma unroll
    for (int i = 0; i < 2; ++i)
#pragma unroll
        for (int j = 0; j < 8; ++j) {
            long row0 = m0 + wm + i * 16 + r;
            long col = n0 + wn + j * 8 + c2;
            *(float2*)&C[row0 * N + col]       = make_float2(acc[i][j][0], acc[i][j][1]);
            *(float2*)&C[(row0 + 8) * N + col] = make_float2(acc[i][j][2], acc[i][j][3]);
        }
}

// ---------------------------------------------------------------------------
// Per-(token, head) RMSNorm + RoPE (unchanged)
// ---------------------------------------------------------------------------
__global__ void __launch_bounds__(128) norm_rope_kernel(float* __restrict__ gq,
                                                        float* __restrict__ gk,
                                                        const float* __restrict__ qw,
                                                        const float* __restrict__ kw) {
    const int s = blockIdx.x;
    const int hy = blockIdx.y;
    float* base;
    const float* w;
    if (hy < NH) { base = gq + (long)s * QD + hy * HD;        w = qw; }
    else         { base = gk + (long)s * KVD + (hy - NH) * HD; w = kw; }

    const int t = threadIdx.x;
    float x = base[t];
    float v = x * x;
#pragma unroll
    for (int off = 16; off; off >>= 1) v += __shfl_xor_sync(0xffffffffu, v, off);

    __shared__ float ws[4];
    __shared__ float xs[128];
    if ((t & 31) == 0) ws[t >> 5] = v;
    __syncthreads();
    float var = (ws[0] + ws[1] + ws[2] + ws[3]) * (1.0f / 128.0f);
    float xn = x * rsqrtf(var + 1e-6f) * w[t];
    xs[t] = xn;
    __syncthreads();

    const int half = t & 63;
    float invf = exp2f(-19.931568569324174f * ((float)half * (1.0f / 64.0f)));
    float ang = (float)s * invf;
    float c = cosf(ang), sn = sinf(ang);
    float rot = (t < 64) ? -xs[t + 64] : xs[t - 64];
    base[t] = xn * c + rot * sn;
}

// ---------------------------------------------------------------------------
// Flash attention on tf32 tensor cores.
// CTA: 256 threads (8 warps), Q tile 128 (16 rows/warp), KV tile 64.
// grid.x reversed so heavy (large-ntiles) CTAs launch first.
// ---------------------------------------------------------------------------
#define AQ 128
#define AK 64
#define AQS 132   // Qs/Ks row stride
#define AVS 68    // Vt/Ps row stride
#define ATTN_SMEM_FLOATS (AQ*AQS + AK*AQS + HD*AVS + AQ*AVS)
#define ATTN_SMEM_BYTES (ATTN_SMEM_FLOATS*4)

__global__ void __launch_bounds__(256) attn_mma(const float* __restrict__ gq,
                                                const float* __restrict__ gk,
                                                const float* __restrict__ gv,
                                                float* __restrict__ gctx) {
    extern __shared__ float sm[];
    float* Qs = sm;                  // [128][132]  (m x k)
    float* Ks = Qs + AQ * AQS;       // [64][132]   (n x k)
    float* Vt = Ks + AK * AQS;       // [128][68]   V^T: (n=d x k=key)
    float* Ps = Vt + HD * AVS;       // [128][68]   P:   (m x k=key)

    const int tid = threadIdx.x;
    const int lane = tid & 31;
    const int warp = tid >> 5;
    const int r = lane >> 2, c4 = lane & 3;
    const int qblk = gridDim.x - 1 - blockIdx.x;   // heavy blocks first
    const int q0 = qblk * AQ;
    const int h = blockIdx.y;
    const int kvh = h >> 2;
    const int qr = warp * 16;
    const float scale = 0.08838834764831845f;   // 1/sqrt(128)

    // Q tile (pre-scaled, tf32-rounded)
    for (int idx = tid; idx < AQ * HD; idx += 256) {
        int rr = idx >> 7, d = idx & 127;
        Qs[rr * AQS + d] = tf32_rna(gq[(long)(q0 + rr) * QD + h * HD + d] * scale);
    }

    float m_run[2] = {-1e30f, -1e30f};
    float l_run[2] = {0.f, 0.f};
    float o[16][4];
#pragma unroll
    for (int f = 0; f < 16; ++f)
#pragma unroll
        for (int x = 0; x < 4; ++x) o[f][x] = 0.f;

    const int row0 = q0 + qr + r;
    const int row1 = row0 + 8;
    const int ntiles = 2 * qblk + 2;

    for (int t = 0; t < ntiles; ++t) {
        const int k0 = t * AK;
        __syncthreads();
        for (int idx = tid; idx < AK * HD; idx += 256) {
            int rr = idx >> 7, d = idx & 127;
            long gi = (long)(k0 + rr) * KVD + kvh * HD + d;
            Ks[rr * AQS + d] = tf32_rna(gk[gi]);
            Vt[d * AVS + rr] = tf32_rna(gv[gi]);
        }
        __syncthreads();

        // S = Q K^T : 16x64 per warp
        float s[8][4];
#pragma unroll
        for (int j = 0; j < 8; ++j)
#pragma unroll
            for (int x = 0; x < 4; ++x) s[j][x] = 0.f;

#pragma unroll
        for (int kk = 0; kk < HD; kk += 8) {
            uint32_t a[4];
            const float* ap = Qs + (qr + r) * AQS + kk + c4;
            a[0] = __float_as_uint(ap[0]);
            a[1] = __float_as_uint(ap[8 * AQS]);
            a[2] = __float_as_uint(ap[4]);
            a[3] = __float_as_uint(ap[8 * AQS + 4]);
#pragma unroll
            for (int j = 0; j < 8; ++j) {
                const float* bp = Ks + (j * 8 + r) * AQS + kk + c4;
                mma_tf32(s[j], a, __float_as_uint(bp[0]), __float_as_uint(bp[4]));
            }
        }

        // online softmax
        const bool dg = (t >= ntiles - 2);
        float mx0 = -1e30f, mx1 = -1e30f;
#pragma unroll
        for (int j = 0; j < 8; ++j) {
            int col = k0 + j * 8 + 2 * c4;
            if (dg) {
                if (col     > row0) s[j][0] = -1e30f;
                if (col + 1 > row0) s[j][1] = -1e30f;
                if (col     > row1) s[j][2] = -1e30f;
                if (col + 1 > row1) s[j][3] = -1e30f;
            }
            mx0 = fmaxf(mx0, fmaxf(s[j][0], s[j][1]));
            mx1 = fmaxf(mx1, fmaxf(s[j][2], s[j][3]));
        }
        mx0 = fmaxf(mx0, __shfl_xor_sync(0xffffffffu, mx0, 1));
        mx0 = fmaxf(mx0, __shfl_xor_sync(0xffffffffu, mx0, 2));
        mx1 = fmaxf(mx1, __shfl_xor_sync(0xffffffffu, mx1, 1));
        mx1 = fmaxf(mx1, __shfl_xor_sync(0xffffffffu, mx1, 2));

        float mn0 = fmaxf(m_run[0], mx0);
        float mn1 = fmaxf(m_run[1], mx1);
        float cr0 = __expf(m_run[0] - mn0);
        float cr1 = __expf(m_run[1] - mn1);
        m_run[0] = mn0; m_run[1] = mn1;

        float sum0 = 0.f, sum1 = 0.f;
#pragma unroll
        for (int j = 0; j < 8; ++j) {
            s[j][0] = __expf(s[j][0] - mn0);
            s[j][1] = __expf(s[j][1] - mn0);
            s[j][2] = __expf(s[j][2] - mn1);
            s[j][3] = __expf(s[j][3] - mn1);
            sum0 += s[j][0] + s[j][1];
            sum1 += s[j][2] + s[j][3];
        }
        sum0 += __shfl_xor_sync(0xffffffffu, sum0, 1);
        sum0 += __shfl_xor_sync(0xffffffffu, sum0, 2);
        sum1 += __shfl_xor_sync(0xffffffffu, sum1, 1);
        sum1 += __shfl_xor_sync(0xffffffffu, sum1, 2);
        l_run[0] = l_run[0] * cr0 + sum0;
        l_run[1] = l_run[1] * cr1 + sum1;

#pragma unroll
        for (int f = 0; f < 16; ++f) {
            o[f][0] *= cr0; o[f][1] *= cr0;
            o[f][2] *= cr1; o[f][3] *= cr1;
        }

        // P -> smem (tf32-rounded); same warp reads back its own rows
#pragma unroll
        for (int j = 0; j < 8; ++j) {
            *(float2*)&Ps[(qr + r) * AVS + j * 8 + 2 * c4] =
                make_float2(tf32_rna(s[j][0]), tf32_rna(s[j][1]));
            *(float2*)&Ps[(qr + r + 8) * AVS + j * 8 + 2 * c4] =
                make_float2(tf32_rna(s[j][2]), tf32_rna(s[j][3]));
        }
        __syncwarp();

        // O += P V   (A = P rows, B = Vt)
#pragma unroll
        for (int kk = 0; kk < AK; kk += 8) {
            uint32_t a[4];
            const float* ap = Ps + (qr + r) * AVS + kk + c4;
            a[0] = __float_as_uint(ap[0]);
            a[1] = __float_as_uint(ap[8 * AVS]);
            a[2] = __float_as_uint(ap[4]);
            a[3] = __float_as_uint(ap[8 * AVS + 4]);
#pragma unroll
            for (int f = 0; f < 16; ++f) {
                const float* bp = Vt + (f * 8 + r) * AVS + kk + c4;
                mma_tf32(o[f], a, __float_as_uint(bp[0]), __float_as_uint(bp[4]));
            }
        }
    }

    // epilogue: normalize + tf32-round (feeds Wo GEMM)
    float inv0 = 1.f / l_run[0];
    float inv1 = 1.f / l_run[1];
#pragma unroll
    for (int f = 0; f < 16; ++f) {
        long base0 = (long)row0 * QD + h * HD + f * 8 + 2 * c4;
        *(float2*)&gctx[base0] =
            make_float2(tf32_rna(o[f][0] * inv0), tf32_rna(o[f][1] * inv0));
        *(float2*)&gctx[base0 + 8L * QD] =
            make_float2(tf32_rna(o[f][2] * inv1), tf32_rna(o[f][3] * inv1));
    }
}

// ---------------------------------------------------------------------------
extern "C" void kernel_launch(void* const* d_in, const int* in_sizes, int n_in,
                              void* d_out, int out_size) {
    const float* hidden = (const float*)d_in[0];
    const float* Wq = (const float*)d_in[3];
    const float* Wk = (const float*)d_in[4];
    const float* Wv = (const float*)d_in[5];
    const float* Wo = (const float*)d_in[6];
    const float* qw = (const float*)d_in[7];
    const float* kw = (const float*)d_in[8];
    float* out = (float*)d_out;

    float *pq, *pk, *pv, *pctx, *phid, *pwq, *pwk, *pwv, *pwo;
    cudaGetSymbolAddress((void**)&pq, g_q);
    cudaGetSymbolAddress((void**)&pk, g_k);
    cudaGetSymbolAddress((void**)&pv, g_v);
    cudaGetSymbolAddress((void**)&pctx, g_ctx);
    cudaGetSymbolAddress((void**)&phid, g_hid_t);
    cudaGetSymbolAddress((void**)&pwq, g_wq_t);
    cudaGetSymbolAddress((void**)&pwk, g_wk_t);
    cudaGetSymbolAddress((void**)&pwv, g_wv_t);
    cudaGetSymbolAddress((void**)&pwo, g_wo_t);

    round_tf32_kernel<<<(SEQ*HIDDEN)/1024, 256>>>(phid, hidden);
    round_tf32_kernel<<<(QD*HIDDEN)/1024, 256>>>(pwq, Wq);
    round_tf32_kernel<<<(KVD*HIDDEN)/1024, 256>>>(pwk, Wk);
    round_tf32_kernel<<<(KVD*HIDDEN)/1024, 256>>>(pwv, Wv);
    round_tf32_kernel<<<(HIDDEN*QD)/1024, 256>>>(pwo, Wo);

    cudaFuncSetAttribute(sgemm_tf32, cudaFuncAttributeMaxDynamicSharedMemorySize,
                         GEMM_SMEM_BYTES);

    sgemm_tf32<<<dim3(QD / 128, SEQ / 128), 256, GEMM_SMEM_BYTES>>>(phid, pwq, pq, SEQ, QD, HIDDEN);
    sgemm_tf32<<<dim3(KVD / 128, SEQ / 128), 256, GEMM_SMEM_BYTES>>>(phid, pwk, pk, SEQ, KVD, HIDDEN);
    sgemm_tf32<<<dim3(KVD / 128, SEQ / 128), 256, GEMM_SMEM_BYTES>>>(phid, pwv, pv, SEQ, KVD, HIDDEN);

    norm_rope_kernel<<<dim3(SEQ, NH + NKV), 128>>>(pq, pk, qw, kw);

    cudaFuncSetAttribute(attn_mma, cudaFuncAttributeMaxDynamicSharedMemorySize,
                         ATTN_SMEM_BYTES);
    attn_mma<<<dim3(SEQ / AQ, NH), 256, ATTN_SMEM_BYTES>>>(pq, pk, pv, pctx);

    sgemm_tf32<<<dim3(HIDDEN / 128, SEQ / 128), 256, GEMM_SMEM_BYTES>>>(pctx, pwo, out, SEQ, HIDDEN, HIDDEN);
}

// round 6
// speedup vs baseline: 5.5451x; 1.6722x over previous
#include <cuda_runtime.h>
#include <cuda_fp16.h>
#include <math.h>
#include <stdint.h>

#define SEQ 2048
#define HIDDEN 4096
#define NH 32
#define NKV 8
#define HD 128
#define QD (NH*HD)     // 4096
#define KVD2 2048      // fused K|V row width

// Scratch (static device globals: allocation-guard-safe)
__device__ float  g_q[SEQ*QD];
__device__ float  g_kv[SEQ*KVD2];         // [token][K 0..1023 | V 1024..2047] fp32
__device__ __half g_ctx_h[SEQ*QD];        // attention output (half, feeds O-proj)
__device__ __half g_hid_h[SEQ*HIDDEN];
__device__ __half g_wq_h[QD*HIDDEN];
__device__ __half g_wkv_h[KVD2*HIDDEN];   // Wk rows then Wv rows
__device__ __half g_wo_h[HIDDEN*QD];

__device__ __forceinline__ void ldm_x4(uint32_t* r, uint32_t addr) {
    asm volatile("ldmatrix.sync.aligned.m8n8.x4.shared.b16 {%0,%1,%2,%3}, [%4];"
        : "=r"(r[0]), "=r"(r[1]), "=r"(r[2]), "=r"(r[3]) : "r"(addr));
}

__device__ __forceinline__ void mma_h(float* d, const uint32_t* a,
                                      uint32_t b0, uint32_t b1) {
    asm volatile(
        "mma.sync.aligned.m16n8k16.row.col.f32.f16.f16.f32 "
        "{%0,%1,%2,%3},{%4,%5,%6,%7},{%8,%9},{%0,%1,%2,%3};\n"
        : "+f"(d[0]), "+f"(d[1]), "+f"(d[2]), "+f"(d[3])
        : "r"(a[0]), "r"(a[1]), "r"(a[2]), "r"(a[3]), "r"(b0), "r"(b1));
}

// ---------------------------------------------------------------------------
// fp32 -> fp16 (RN). 8 elements/thread.
// ---------------------------------------------------------------------------
__global__ void __launch_bounds__(256) round_h_kernel(__half* __restrict__ dst,
                                                      const float* __restrict__ src) {
    long i = ((long)blockIdx.x * 256 + threadIdx.x) * 8;
    float4 v0 = *(const float4*)(src + i);
    float4 v1 = *(const float4*)(src + i + 4);
    __half2 h[4];
    h[0] = __floats2half2_rn(v0.x, v0.y);
    h[1] = __floats2half2_rn(v0.z, v0.w);
    h[2] = __floats2half2_rn(v1.x, v1.y);
    h[3] = __floats2half2_rn(v1.z, v1.w);
    *(uint4*)(dst + i) = *(uint4*)h;
}

// ---------------------------------------------------------------------------
// fp16 tensor-core GEMM: C[m,n] = sum_k A[m*K+k]*B[n*K+k], fp32 accum.
// 128x128 tile, BK=32, 256 threads (8 warps: 4(m) x 2(n), warp tile 32x64),
// ldmatrix + mma.m16n8k16, 3-stage cp.async pipeline.
// ---------------------------------------------------------------------------
#define SA_H 40                          // smem stride (halves); 80B, conflict-free
#define STG_HALF_BYTES (128*SA_H*2)      // 10240 per operand tile
#define STAGE_BYTES (2*STG_HALF_BYTES)   // 20480
#define NST 3
#define GEMM_SMEM_BYTES (NST*STAGE_BYTES)

__global__ void __launch_bounds__(256) hgemm(const __half* __restrict__ A,
                                             const __half* __restrict__ B,
                                             float* __restrict__ C,
                                             int N, int K) {
    extern __shared__ char smraw[];
    uint32_t sbase = (uint32_t)__cvta_generic_to_shared(smraw);
    const int tid = threadIdx.x;
    const int lane = tid & 31;
    const int warp = tid >> 5;
    const int wm = (warp & 3) * 32;
    const int wn = (warp >> 2) * 64;
    const int m0 = blockIdx.y * 128, n0 = blockIdx.x * 128;

    float acc[2][8][4];
#pragma unroll
    for (int i = 0; i < 2; ++i)
#pragma unroll
        for (int j = 0; j < 8; ++j)
#pragma unroll
            for (int x = 0; x < 4; ++x) acc[i][j][x] = 0.f;

    const int nk = K >> 5;

    auto prefetch = [&](int t) {
        int slot = t % NST;
        uint32_t sa = sbase + slot * STAGE_BYTES;
        uint32_t sb = sa + STG_HALF_BYTES;
        int k0 = t << 5;
#pragma unroll
        for (int i = 0; i < 2; ++i) {
            int c = tid + i * 256;               // 0..511
            int row = c >> 2, cc = c & 3;
            uint32_t da = sa + row * 80 + cc * 16;
            const __half* ga = A + (long)(m0 + row) * K + k0 + cc * 8;
            asm volatile("cp.async.cg.shared.global [%0], [%1], 16;\n" :: "r"(da), "l"(ga));
            uint32_t db = sb + row * 80 + cc * 16;
            const __half* gb = B + (long)(n0 + row) * K + k0 + cc * 8;
            asm volatile("cp.async.cg.shared.global [%0], [%1], 16;\n" :: "r"(db), "l"(gb));
        }
        asm volatile("cp.async.commit_group;\n");
    };

    prefetch(0);
    prefetch(1);

    // per-thread ldmatrix address components
    const int aRow = lane & 15;                  // + wm + i*16
    const int aCol = 8 * (lane >> 4);
    const int bRow = (lane & 7) + ((lane >> 4) & 1) * 8;   // + wn + jp*16
    const int bCol = ((lane >> 3) & 1) * 8;

    for (int t = 0; t < nk; ++t) {
        if (t + 2 < nk) {
            prefetch(t + 2);
            asm volatile("cp.async.wait_group 2;\n");
        } else {
            asm volatile("cp.async.wait_group 0;\n");
        }
        __syncthreads();

        uint32_t sa = sbase + (t % NST) * STAGE_BYTES;
        uint32_t sb = sa + STG_HALF_BYTES;

#pragma unroll
        for (int kk = 0; kk < 32; kk += 16) {
            uint32_t a[2][4];
#pragma unroll
            for (int i = 0; i < 2; ++i)
                ldm_x4(a[i], sa + ((wm + i * 16 + aRow) * SA_H + kk + aCol) * 2);
            uint32_t b[8][2];
#pragma unroll
            for (int jp = 0; jp < 4; ++jp) {
                uint32_t bb[4];
                ldm_x4(bb, sb + ((wn + jp * 16 + bRow) * SA_H + kk + bCol) * 2);
                b[2 * jp][0] = bb[0]; b[2 * jp][1] = bb[1];
                b[2 * jp + 1][0] = bb[2]; b[2 * jp + 1][1] = bb[3];
            }
#pragma unroll
            for (int i = 0; i < 2; ++i)
#pragma unroll
                for (int j = 0; j < 8; ++j)
                    mma_h(acc[i][j], a[i], b[j][0], b[j][1]);
        }
        __syncthreads();
    }

    const int r = lane >> 2, c2 = (lane & 3) * 2;
#pragma unroll
    for (int i = 0; i < 2; ++i)
#pragma unroll
        for (int j = 0; j < 8; ++j) {
            long row0 = m0 + wm + i * 16 + r;
            long col = n0 + wn + j * 8 + c2;
            *(float2*)&C[row0 * N + col]       = make_float2(acc[i][j][0], acc[i][j][1]);
            *(float2*)&C[(row0 + 8) * N + col] = make_float2(acc[i][j][2], acc[i][j][3]);
        }
}

// ---------------------------------------------------------------------------
// Per-(token, head) RMSNorm + RoPE. Q heads and K heads (K lives in g_kv).
// ---------------------------------------------------------------------------
__global__ void __launch_bounds__(128) norm_rope_kernel(float* __restrict__ gq,
                                                        float* __restrict__ gkv,
                                                        const float* __restrict__ qw,
                                                        const float* __restrict__ kw) {
    const int s = blockIdx.x;
    const int hy = blockIdx.y;
    float* base;
    const float* w;
    if (hy < NH) { base = gq + (long)s * QD + hy * HD;           w = qw; }
    else         { base = gkv + (long)s * KVD2 + (hy - NH) * HD; w = kw; }

    const int t = threadIdx.x;
    float x = base[t];
    float v = x * x;
#pragma unroll
    for (int off = 16; off; off >>= 1) v += __shfl_xor_sync(0xffffffffu, v, off);

    __shared__ float ws[4];
    __shared__ float xs[128];
    if ((t & 31) == 0) ws[t >> 5] = v;
    __syncthreads();
    float var = (ws[0] + ws[1] + ws[2] + ws[3]) * (1.0f / 128.0f);
    float xn = x * rsqrtf(var + 1e-6f) * w[t];
    xs[t] = xn;
    __syncthreads();

    const int half = t & 63;
    float invf = exp2f(-19.931568569324174f * ((float)half * (1.0f / 64.0f)));
    float ang = (float)s * invf;
    float c = cosf(ang), sn = sinf(ang);
    float rot = (t < 64) ? -xs[t + 64] : xs[t - 64];
    base[t] = xn * c + rot * sn;
}

// ---------------------------------------------------------------------------
// Flash attention on fp16 mma (legacy pipe). Q tile 128, KV tile 64.
// 256 threads / 8 warps, 16 q-rows per warp. ctx written as fp16.
// ---------------------------------------------------------------------------
#define AQ 128
#define AK 64
#define QSH 136   // Qs/Ks stride (halves) = 272B
#define VSH 72    // Vt/Ps stride (halves) = 144B
#define ATTN_SMEM_HALVES (AQ*QSH + AK*QSH + HD*VSH + AQ*VSH)
#define ATTN_SMEM_BYTES (ATTN_SMEM_HALVES*2)

__global__ void __launch_bounds__(256) attn_mma(const float* __restrict__ gq,
                                                const float* __restrict__ gkv,
                                                __half* __restrict__ gctx) {
    extern __shared__ __half smh[];
    __half* Qs = smh;                 // [128][136]  (m x d)
    __half* Ks = Qs + AQ * QSH;       // [64][136]   (n x d)
    __half* Vt = Ks + AK * QSH;       // [128][72]   V^T: (d x key)
    __half* Ps = Vt + HD * VSH;       // [128][72]   P:   (m x key)
    uint32_t qs_a = (uint32_t)__cvta_generic_to_shared(Qs);
    uint32_t ks_a = (uint32_t)__cvta_generic_to_shared(Ks);
    uint32_t vt_a = (uint32_t)__cvta_generic_to_shared(Vt);
    uint32_t ps_a = (uint32_t)__cvta_generic_to_shared(Ps);

    const int tid = threadIdx.x;
    const int lane = tid & 31;
    const int warp = tid >> 5;
    const int r = lane >> 2, c4 = lane & 3;
    const int qblk = gridDim.x - 1 - blockIdx.x;   // heavy blocks first
    const int q0 = qblk * AQ;
    const int h = blockIdx.y;
    const int kvh = h >> 2;
    const int qr = warp * 16;
    const float scale = 0.08838834764831845f;      // 1/sqrt(128)

    const int aRow = lane & 15;
    const int aCol = 8 * (lane >> 4);
    const int bRow = (lane & 7) + ((lane >> 4) & 1) * 8;
    const int bCol = ((lane >> 3) & 1) * 8;

    // Q tile (pre-scaled, fp16)
    for (int idx = tid; idx < AQ * HD / 4; idx += 256) {
        int rr = idx >> 5, d4 = (idx & 31) * 4;
        float4 qv = *(const float4*)&gq[(long)(q0 + rr) * QD + h * HD + d4];
        *(__half2*)&Qs[rr * QSH + d4]     = __floats2half2_rn(qv.x * scale, qv.y * scale);
        *(__half2*)&Qs[rr * QSH + d4 + 2] = __floats2half2_rn(qv.z * scale, qv.w * scale);
    }

    float m_run[2] = {-1e30f, -1e30f};
    float l_run[2] = {0.f, 0.f};
    float o[16][4];
#pragma unroll
    for (int f = 0; f < 16; ++f)
#pragma unroll
        for (int x = 0; x < 4; ++x) o[f][x] = 0.f;

    const int row0 = q0 + qr + r;
    const int row1 = row0 + 8;
    const int ntiles = 2 * qblk + 2;

    for (int t = 0; t < ntiles; ++t) {
        const int k0 = t * AK;
        __syncthreads();
        for (int idx = tid; idx < AK * HD / 4; idx += 256) {
            int rr = idx >> 5, d4 = (idx & 31) * 4;
            long gi = (long)(k0 + rr) * KVD2 + kvh * HD + d4;
            float4 kv = *(const float4*)&gkv[gi];
            *(__half2*)&Ks[rr * QSH + d4]     = __floats2half2_rn(kv.x, kv.y);
            *(__half2*)&Ks[rr * QSH + d4 + 2] = __floats2half2_rn(kv.z, kv.w);
            float4 vv = *(const float4*)&gkv[gi + 1024];
            Vt[(d4 + 0) * VSH + rr] = __float2half_rn(vv.x);
            Vt[(d4 + 1) * VSH + rr] = __float2half_rn(vv.y);
            Vt[(d4 + 2) * VSH + rr] = __float2half_rn(vv.z);
            Vt[(d4 + 3) * VSH + rr] = __float2half_rn(vv.w);
        }
        __syncthreads();

        // S = Q K^T : 16x64 per warp
        float s[8][4];
#pragma unroll
        for (int j = 0; j < 8; ++j)
#pragma unroll
            for (int x = 0; x < 4; ++x) s[j][x] = 0.f;

#pragma unroll
        for (int kk = 0; kk < HD; kk += 16) {
            uint32_t a[4];
            ldm_x4(a, qs_a + ((qr + aRow) * QSH + kk + aCol) * 2);
#pragma unroll
            for (int jp = 0; jp < 4; ++jp) {
                uint32_t bb[4];
                ldm_x4(bb, ks_a + ((jp * 16 + bRow) * QSH + kk + bCol) * 2);
                mma_h(s[2 * jp],     a, bb[0], bb[1]);
                mma_h(s[2 * jp + 1], a, bb[2], bb[3]);
            }
        }

        // online softmax
        const bool dg = (t >= ntiles - 2);
        float mx0 = -1e30f, mx1 = -1e30f;
#pragma unroll
        for (int j = 0; j < 8; ++j) {
            int col = k0 + j * 8 + 2 * c4;
            if (dg) {
                if (col     > row0) s[j][0] = -1e30f;
                if (col + 1 > row0) s[j][1] = -1e30f;
                if (col     > row1) s[j][2] = -1e30f;
                if (col + 1 > row1) s[j][3] = -1e30f;
            }
            mx0 = fmaxf(mx0, fmaxf(s[j][0], s[j][1]));
            mx1 = fmaxf(mx1, fmaxf(s[j][2], s[j][3]));
        }
        mx0 = fmaxf(mx0, __shfl_xor_sync(0xffffffffu, mx0, 1));
        mx0 = fmaxf(mx0, __shfl_xor_sync(0xffffffffu, mx0, 2));
        mx1 = fmaxf(mx1, __shfl_xor_sync(0xffffffffu, mx1, 1));
        mx1 = fmaxf(mx1, __shfl_xor_sync(0xffffffffu, mx1, 2));

        float mn0 = fmaxf(m_run[0], mx0);
        float mn1 = fmaxf(m_run[1], mx1);
        float cr0 = __expf(m_run[0] - mn0);
        float cr1 = __expf(m_run[1] - mn1);
        m_run[0] = mn0; m_run[1] = mn1;

        float sum0 = 0.f, sum1 = 0.f;
#pragma unroll
        for (int j = 0; j < 8; ++j) {
            s[j][0] = __expf(s[j][0] - mn0);
            s[j][1] = __expf(s[j][1] - mn0);
            s[j][2] = __expf(s[j][2] - mn1);
            s[j][3] = __expf(s[j][3] - mn1);
            sum0 += s[j][0] + s[j][1];
            sum1 += s[j][2] + s[j][3];
        }
        sum0 += __shfl_xor_sync(0xffffffffu, sum0, 1);
        sum0 += __shfl_xor_sync(0xffffffffu, sum0, 2);
        sum1 += __shfl_xor_sync(0xffffffffu, sum1, 1);
        sum1 += __shfl_xor_sync(0xffffffffu, sum1, 2);
        l_run[0] = l_run[0] * cr0 + sum0;
        l_run[1] = l_run[1] * cr1 + sum1;

#pragma unroll
        for (int f = 0; f < 16; ++f) {
            o[f][0] *= cr0; o[f][1] *= cr0;
            o[f][2] *= cr1; o[f][3] *= cr1;
        }

        // P -> smem (fp16); same warp reads back only its own 16 rows
#pragma unroll
        for (int j = 0; j < 8; ++j) {
            *(__half2*)&Ps[(qr + r) * VSH + j * 8 + 2 * c4] =
                __floats2half2_rn(s[j][0], s[j][1]);
            *(__half2*)&Ps[(qr + r + 8) * VSH + j * 8 + 2 * c4] =
                __floats2half2_rn(s[j][2], s[j][3]);
        }
        __syncwarp();

        // O += P V
#pragma unroll
        for (int kk = 0; kk < AK; kk += 16) {
            uint32_t a[4];
            ldm_x4(a, ps_a + ((qr + aRow) * VSH + kk + aCol) * 2);
#pragma unroll
            for (int fp = 0; fp < 8; ++fp) {
                uint32_t bb[4];
                ldm_x4(bb, vt_a + ((fp * 16 + bRow) * VSH + kk + bCol) * 2);
                mma_h(o[2 * fp],     a, bb[0], bb[1]);
                mma_h(o[2 * fp + 1], a, bb[2], bb[3]);
            }
        }
    }

    // epilogue: normalize + fp16 (feeds Wo GEMM)
    float inv0 = 1.f / l_run[0];
    float inv1 = 1.f / l_run[1];
#pragma unroll
    for (int f = 0; f < 16; ++f) {
        long base0 = (long)row0 * QD + h * HD + f * 8 + 2 * c4;
        *(__half2*)&gctx[base0] =
            __floats2half2_rn(o[f][0] * inv0, o[f][1] * inv0);
        *(__half2*)&gctx[base0 + 8L * QD] =
            __floats2half2_rn(o[f][2] * inv1, o[f][3] * inv1);
    }
}

// ---------------------------------------------------------------------------
extern "C" void kernel_launch(void* const* d_in, const int* in_sizes, int n_in,
                              void* d_out, int out_size) {
    const float* hidden = (const float*)d_in[0];
    const float* Wq = (const float*)d_in[3];
    const float* Wk = (const float*)d_in[4];
    const float* Wv = (const float*)d_in[5];
    const float* Wo = (const float*)d_in[6];
    const float* qw = (const float*)d_in[7];
    const float* kw = (const float*)d_in[8];
    float* out = (float*)d_out;

    float *pq, *pkv;
    __half *pctx, *phid, *pwq, *pwkv, *pwo;
    cudaGetSymbolAddress((void**)&pq, g_q);
    cudaGetSymbolAddress((void**)&pkv, g_kv);
    cudaGetSymbolAddress((void**)&pctx, g_ctx_h);
    cudaGetSymbolAddress((void**)&phid, g_hid_h);
    cudaGetSymbolAddress((void**)&pwq, g_wq_h);
    cudaGetSymbolAddress((void**)&pwkv, g_wkv_h);
    cudaGetSymbolAddress((void**)&pwo, g_wo_h);

    // fp32 -> fp16 rounding (Wk,Wv fused into one B buffer)
    round_h_kernel<<<(SEQ*HIDDEN)/2048, 256>>>(phid, hidden);
    round_h_kernel<<<(QD*HIDDEN)/2048, 256>>>(pwq, Wq);
    round_h_kernel<<<(1024*HIDDEN)/2048, 256>>>(pwkv, Wk);
    round_h_kernel<<<(1024*HIDDEN)/2048, 256>>>(pwkv + 1024*HIDDEN, Wv);
    round_h_kernel<<<(HIDDEN*QD)/2048, 256>>>(pwo, Wo);

    cudaFuncSetAttribute(hgemm, cudaFuncAttributeMaxDynamicSharedMemorySize,
                         GEMM_SMEM_BYTES);

    // Q projection + fused KV projection (fp16 tensor cores)
    hgemm<<<dim3(QD / 128, SEQ / 128), 256, GEMM_SMEM_BYTES>>>(phid, pwq, pq, QD, HIDDEN);
    hgemm<<<dim3(KVD2 / 128, SEQ / 128), 256, GEMM_SMEM_BYTES>>>(phid, pwkv, pkv, KVD2, HIDDEN);

    norm_rope_kernel<<<dim3(SEQ, NH + NKV), 128>>>(pq, pkv, qw, kw);

    cudaFuncSetAttribute(attn_mma, cudaFuncAttributeMaxDynamicSharedMemorySize,
                         ATTN_SMEM_BYTES);
    attn_mma<<<dim3(SEQ / AQ, NH), 256, ATTN_SMEM_BYTES>>>(pq, pkv, pctx);

    // Output projection -> d_out (fp16 tensor cores, fp32 out)
    hgemm<<<dim3(HIDDEN / 128, SEQ / 128), 256, GEMM_SMEM_BYTES>>>(pctx, pwo, out, HIDDEN, HIDDEN);
}

// round 7
// speedup vs baseline: 7.6668x; 1.3826x over previous
#include <cuda_runtime.h>
#include <cuda_fp16.h>
#include <math.h>
#include <stdint.h>

#define SEQ 2048
#define HIDDEN 4096
#define NH 32
#define NKV 8
#define HD 128
#define QD (NH*HD)     // 4096
#define N1 6144        // fused Q|K|V output width

// Scratch (static device globals)
__device__ float  g_qkv[SEQ*N1];          // fused QKV projection output (fp32)
__device__ __half g_hid_h[SEQ*HIDDEN];
__device__ __half g_w1_h[N1*HIDDEN];      // [Wq rows | Wk rows | Wv rows]
__device__ __half g_wo_h[HIDDEN*QD];
__device__ __half g_q_h[SEQ*QD];          // normed+roped+scaled Q
__device__ __half g_k_h[SEQ*1024];        // normed+roped K
__device__ __half g_vt[1024*SEQ];         // V transposed: [kvh*128+d][token]
__device__ __half g_ctx_h[SEQ*QD];

__device__ __forceinline__ void ldm_x4(uint32_t* r, uint32_t addr) {
    asm volatile("ldmatrix.sync.aligned.m8n8.x4.shared.b16 {%0,%1,%2,%3}, [%4];"
        : "=r"(r[0]), "=r"(r[1]), "=r"(r[2]), "=r"(r[3]) : "r"(addr));
}

__device__ __forceinline__ void mma_h(float* d, const uint32_t* a,
                                      uint32_t b0, uint32_t b1) {
    asm volatile(
        "mma.sync.aligned.m16n8k16.row.col.f32.f16.f16.f32 "
        "{%0,%1,%2,%3},{%4,%5,%6,%7},{%8,%9},{%0,%1,%2,%3};\n"
        : "+f"(d[0]), "+f"(d[1]), "+f"(d[2]), "+f"(d[3])
        : "r"(a[0]), "r"(a[1]), "r"(a[2]), "r"(a[3]), "r"(b0), "r"(b1));
}

// ---------------------------------------------------------------------------
__global__ void __launch_bounds__(256) round_h_kernel(__half* __restrict__ dst,
                                                      const float* __restrict__ src) {
    long i = ((long)blockIdx.x * 256 + threadIdx.x) * 8;
    float4 v0 = *(const float4*)(src + i);
    float4 v1 = *(const float4*)(src + i + 4);
    __half2 h[4];
    h[0] = __floats2half2_rn(v0.x, v0.y);
    h[1] = __floats2half2_rn(v0.z, v0.w);
    h[2] = __floats2half2_rn(v1.x, v1.y);
    h[3] = __floats2half2_rn(v1.z, v1.w);
    *(uint4*)(dst + i) = *(uint4*)h;
}

// ---------------------------------------------------------------------------
// fp16 GEMM: C[m,n] = sum_k A[m*K+k]*B[n*K+k], fp32 accum.
// 128x128 tile, BK=64, 256 threads, 3-stage cp.async, 2 CTAs/SM.
// ---------------------------------------------------------------------------
#define SA_H 72                          // halves; 144B rows, conflict-free
#define STG_OP_BYTES (128*SA_H*2)        // 18432 per operand
#define STAGE_BYTES (2*STG_OP_BYTES)     // 36864
#define NST 3
#define GEMM_SMEM_BYTES (NST*STAGE_BYTES)  // 110592

__global__ void __launch_bounds__(256, 2) hgemm(const __half* __restrict__ A,
                                                const __half* __restrict__ B,
                                                float* __restrict__ C,
                                                int N, int K) {
    extern __shared__ char smraw[];
    uint32_t sbase = (uint32_t)__cvta_generic_to_shared(smraw);
    const int tid = threadIdx.x;
    const int lane = tid & 31;
    const int warp = tid >> 5;
    const int wm = (warp & 3) * 32;
    const int wn = (warp >> 2) * 64;
    const int m0 = blockIdx.y * 128, n0 = blockIdx.x * 128;

    float acc[2][8][4];
#pragma unroll
    for (int i = 0; i < 2; ++i)
#pragma unroll
        for (int j = 0; j < 8; ++j)
#pragma unroll
            for (int x = 0; x < 4; ++x) acc[i][j][x] = 0.f;

    const int nk = K >> 6;

    auto prefetch = [&](int t) {
        int slot = t % NST;
        uint32_t sa = sbase + slot * STAGE_BYTES;
        uint32_t sb = sa + STG_OP_BYTES;
        int k0 = t << 6;
#pragma unroll
        for (int i = 0; i < 4; ++i) {
            int c = tid + i * 256;               // 0..1023
            int row = c >> 3, cc = c & 7;
            uint32_t da = sa + row * 144 + cc * 16;
            const __half* ga = A + (long)(m0 + row) * K + k0 + cc * 8;
            asm volatile("cp.async.cg.shared.global [%0], [%1], 16;\n" :: "r"(da), "l"(ga));
            uint32_t db = sb + row * 144 + cc * 16;
            const __half* gb = B + (long)(n0 + row) * K + k0 + cc * 8;
            asm volatile("cp.async.cg.shared.global [%0], [%1], 16;\n" :: "r"(db), "l"(gb));
        }
        asm volatile("cp.async.commit_group;\n");
    };

    prefetch(0);
    prefetch(1);

    const int aRow = lane & 15;
    const int aCol = 8 * (lane >> 4);
    const int bRow = (lane & 7) + ((lane >> 4) & 1) * 8;
    const int bCol = ((lane >> 3) & 1) * 8;

    for (int t = 0; t < nk; ++t) {
        if (t + 2 < nk) {
            prefetch(t + 2);
            asm volatile("cp.async.wait_group 2;\n");
        } else {
            asm volatile("cp.async.wait_group 0;\n");
        }
        __syncthreads();

        uint32_t sa = sbase + (t % NST) * STAGE_BYTES;
        uint32_t sb = sa + STG_OP_BYTES;

#pragma unroll
        for (int kk = 0; kk < 64; kk += 16) {
            uint32_t a[2][4];
#pragma unroll
            for (int i = 0; i < 2; ++i)
                ldm_x4(a[i], sa + ((wm + i * 16 + aRow) * SA_H + kk + aCol) * 2);
            uint32_t b[8][2];
#pragma unroll
            for (int jp = 0; jp < 4; ++jp) {
                uint32_t bb[4];
                ldm_x4(bb, sb + ((wn + jp * 16 + bRow) * SA_H + kk + bCol) * 2);
                b[2 * jp][0] = bb[0]; b[2 * jp][1] = bb[1];
                b[2 * jp + 1][0] = bb[2]; b[2 * jp + 1][1] = bb[3];
            }
#pragma unroll
            for (int i = 0; i < 2; ++i)
#pragma unroll
                for (int j = 0; j < 8; ++j)
                    mma_h(acc[i][j], a[i], b[j][0], b[j][1]);
        }
        __syncthreads();
    }

    const int r = lane >> 2, c2 = (lane & 3) * 2;
#pragma unroll
    for (int i = 0; i < 2; ++i)
#pragma unroll
        for (int j = 0; j < 8; ++j) {
            long row0 = m0 + wm + i * 16 + r;
            long col = n0 + wn + j * 8 + c2;
            *(float2*)&C[row0 * N + col]       = make_float2(acc[i][j][0], acc[i][j][1]);
            *(float2*)&C[(row0 + 8) * N + col] = make_float2(acc[i][j][2], acc[i][j][3]);
        }
}

// ---------------------------------------------------------------------------
// RMSNorm + RoPE from fused QKV buffer; writes fp16.
// grid.y: 0..31 Q heads (scaled by 1/sqrt(128)), 32..39 K heads.
// ---------------------------------------------------------------------------
__global__ void __launch_bounds__(128) norm_rope_kernel(const float* __restrict__ qkv,
                                                        __half* __restrict__ qh,
                                                        __half* __restrict__ kh,
                                                        const float* __restrict__ qw,
                                                        const float* __restrict__ kw) {
    const int s = blockIdx.x;
    const int hy = blockIdx.y;
    const int t = threadIdx.x;
    const bool isq = hy < NH;
    const float* src = qkv + (long)s * N1 + (isq ? hy * HD : HIDDEN + (hy - NH) * HD);
    const float* w = isq ? qw : kw;

    float x = src[t];
    float v = x * x;
#pragma unroll
    for (int off = 16; off; off >>= 1) v += __shfl_xor_sync(0xffffffffu, v, off);

    __shared__ float ws[4];
    __shared__ float xs[128];
    if ((t & 31) == 0) ws[t >> 5] = v;
    __syncthreads();
    float var = (ws[0] + ws[1] + ws[2] + ws[3]) * (1.0f / 128.0f);
    float xn = x * rsqrtf(var + 1e-6f) * w[t];
    xs[t] = xn;
    __syncthreads();

    const int half = t & 63;
    float invf = exp2f(-19.931568569324174f * ((float)half * (1.0f / 64.0f)));
    float ang = (float)s * invf;
    float c = cosf(ang), sn = sinf(ang);
    float rot = (t < 64) ? -xs[t + 64] : xs[t - 64];
    float y = xn * c + rot * sn;

    if (isq)
        qh[(long)s * QD + hy * HD + t] = __float2half_rn(y * 0.08838834764831845f);
    else
        kh[(long)s * 1024 + (hy - NH) * HD + t] = __float2half_rn(y);
}

// ---------------------------------------------------------------------------
// V transpose: g_qkv[s][5120+j] (fp32) -> g_vt[j][s] (fp16). 32x32 tiles.
// ---------------------------------------------------------------------------
__global__ void __launch_bounds__(256) vtrans_kernel(const float* __restrict__ qkv,
                                                     __half* __restrict__ vt) {
    __shared__ __half tile[32][33];
    const int s0 = blockIdx.x * 32, j0 = blockIdx.y * 32;
    const int tx = threadIdx.x & 31, ty = threadIdx.x >> 5;   // 32 x 8
#pragma unroll
    for (int yy = 0; yy < 4; ++yy) {
        int sr = ty + yy * 8;
        tile[sr][tx] = __float2half_rn(qkv[(long)(s0 + sr) * N1 + 5120 + j0 + tx]);
    }
    __syncthreads();
#pragma unroll
    for (int yy = 0; yy < 4; ++yy) {
        int jr = ty + yy * 8;
        vt[(long)(j0 + jr) * SEQ + s0 + tx] = tile[tx][jr];
    }
}

// ---------------------------------------------------------------------------
// Flash attention, fp16 mma, cp.async double-buffered K/V tiles.
// Q tile 128, KV tile 64, 256 threads / 8 warps.
// ---------------------------------------------------------------------------
#define AQ 128
#define AK 64
#define QSH 136   // halves (272B rows)
#define VSH 72    // halves (144B rows)
// smem (halves): Qs 128*136 | Ks[2] 64*136 | Vt[2] 128*72 | Ps 128*72
#define OFF_QS 0
#define OFF_KS 17408
#define OFF_VT (17408 + 2*8704)
#define OFF_PS (OFF_VT + 2*9216)
#define ATTN_SMEM_BYTES ((OFF_PS + 9216)*2)

__global__ void __launch_bounds__(256) attn_mma(const __half* __restrict__ gq,
                                                const __half* __restrict__ gk,
                                                const __half* __restrict__ gvt,
                                                __half* __restrict__ gctx) {
    extern __shared__ __half smh[];
    uint32_t sb = (uint32_t)__cvta_generic_to_shared(smh);
    const uint32_t qs_a = sb + OFF_QS * 2;
    const uint32_t ps_a = sb + OFF_PS * 2;

    const int tid = threadIdx.x;
    const int lane = tid & 31;
    const int warp = tid >> 5;
    const int r = lane >> 2, c4 = lane & 3;
    const int qblk = gridDim.x - 1 - blockIdx.x;   // heavy blocks first
    const int q0 = qblk * AQ;
    const int h = blockIdx.y;
    const int kvh = h >> 2;
    const int qr = warp * 16;

    const int aRow = lane & 15;
    const int aCol = 8 * (lane >> 4);
    const int bRow = (lane & 7) + ((lane >> 4) & 1) * 8;
    const int bCol = ((lane >> 3) & 1) * 8;

    const int ntiles = 2 * qblk + 2;

    // K/V tile prefetch into slot t&1
    auto fill = [&](int t) {
        int slot = t & 1;
        int k0 = t * AK;
        uint32_t ka = sb + (OFF_KS + slot * 8704) * 2;
        uint32_t va = sb + (OFF_VT + slot * 9216) * 2;
#pragma unroll
        for (int i = 0; i < 4; ++i) {               // K: 64 rows x 16 chunks
            int idx = tid + i * 256;
            int row = idx >> 4, cc = idx & 15;
            uint32_t dst = ka + row * 272 + cc * 16;
            const __half* src = gk + (long)(k0 + row) * 1024 + kvh * HD + cc * 8;
            asm volatile("cp.async.cg.shared.global [%0], [%1], 16;\n" :: "r"(dst), "l"(src));
        }
#pragma unroll
        for (int i = 0; i < 4; ++i) {               // V^T: 128 rows x 8 chunks
            int idx = tid + i * 256;
            int row = idx >> 3, cc = idx & 7;
            uint32_t dst = va + row * 144 + cc * 16;
            const __half* src = gvt + (long)(kvh * HD + row) * SEQ + k0 + cc * 8;
            asm volatile("cp.async.cg.shared.global [%0], [%1], 16;\n" :: "r"(dst), "l"(src));
        }
        asm volatile("cp.async.commit_group;\n");
    };

    fill(0);

    // Q tile (pre-scaled fp16 in global)
    for (int i = 0; i < 8; ++i) {
        int idx = tid + i * 256;                    // 128 rows x 16 chunks
        int row = idx >> 4, cc = idx & 15;
        *(uint4*)(smh + OFF_QS + row * QSH + cc * 8) =
            *(const uint4*)(gq + (long)(q0 + row) * QD + h * HD + cc * 8);
    }

    float m_run[2] = {-1e30f, -1e30f};
    float l_run[2] = {0.f, 0.f};
    float o[16][4];
#pragma unroll
    for (int f = 0; f < 16; ++f)
#pragma unroll
        for (int x = 0; x < 4; ++x) o[f][x] = 0.f;

    const int row0 = q0 + qr + r;
    const int row1 = row0 + 8;

    for (int t = 0; t < ntiles; ++t) {
        const int k0 = t * AK;
        __syncthreads();                            // slot (t+1)&1 free to refill
        if (t + 1 < ntiles) {
            fill(t + 1);
            asm volatile("cp.async.wait_group 1;\n");
        } else {
            asm volatile("cp.async.wait_group 0;\n");
        }
        __syncthreads();                            // stage t visible to all

        const uint32_t ks_a = sb + (OFF_KS + (t & 1) * 8704) * 2;
        const uint32_t vt_a = sb + (OFF_VT + (t & 1) * 9216) * 2;

        // S = Q K^T : 16x64 per warp
        float s[8][4];
#pragma unroll
        for (int j = 0; j < 8; ++j)
#pragma unroll
            for (int x = 0; x < 4; ++x) s[j][x] = 0.f;

#pragma unroll
        for (int kk = 0; kk < HD; kk += 16) {
            uint32_t a[4];
            ldm_x4(a, qs_a + ((qr + aRow) * QSH + kk + aCol) * 2);
#pragma unroll
            for (int jp = 0; jp < 4; ++jp) {
                uint32_t bb[4];
                ldm_x4(bb, ks_a + ((jp * 16 + bRow) * QSH + kk + bCol) * 2);
                mma_h(s[2 * jp],     a, bb[0], bb[1]);
                mma_h(s[2 * jp + 1], a, bb[2], bb[3]);
            }
        }

        // online softmax
        const bool dg = (t >= ntiles - 2);
        float mx0 = -1e30f, mx1 = -1e30f;
#pragma unroll
        for (int j = 0; j < 8; ++j) {
            int col = k0 + j * 8 + 2 * c4;
            if (dg) {
                if (col     > row0) s[j][0] = -1e30f;
                if (col + 1 > row0) s[j][1] = -1e30f;
                if (col     > row1) s[j][2] = -1e30f;
                if (col + 1 > row1) s[j][3] = -1e30f;
            }
            mx0 = fmaxf(mx0, fmaxf(s[j][0], s[j][1]));
            mx1 = fmaxf(mx1, fmaxf(s[j][2], s[j][3]));
        }
        mx0 = fmaxf(mx0, __shfl_xor_sync(0xffffffffu, mx0, 1));
        mx0 = fmaxf(mx0, __shfl_xor_sync(0xffffffffu, mx0, 2));
        mx1 = fmaxf(mx1, __shfl_xor_sync(0xffffffffu, mx1, 1));
        mx1 = fmaxf(mx1, __shfl_xor_sync(0xffffffffu, mx1, 2));

        float mn0 = fmaxf(m_run[0], mx0);
        float mn1 = fmaxf(m_run[1], mx1);
        float cr0 = __expf(m_run[0] - mn0);
        float cr1 = __expf(m_run[1] - mn1);
        m_run[0] = mn0; m_run[1] = mn1;

        float sum0 = 0.f, sum1 = 0.f;
#pragma unroll
        for (int j = 0; j < 8; ++j) {
            s[j][0] = __expf(s[j][0] - mn0);
            s[j][1] = __expf(s[j][1] - mn0);
            s[j][2] = __expf(s[j][2] - mn1);
            s[j][3] = __expf(s[j][3] - mn1);
            sum0 += s[j][0] + s[j][1];
            sum1 += s[j][2] + s[j][3];
        }
        sum0 += __shfl_xor_sync(0xffffffffu, sum0, 1);
        sum0 += __shfl_xor_sync(0xffffffffu, sum0, 2);
        sum1 += __shfl_xor_sync(0xffffffffu, sum1, 1);
        sum1 += __shfl_xor_sync(0xffffffffu, sum1, 2);
        l_run[0] = l_run[0] * cr0 + sum0;
        l_run[1] = l_run[1] * cr1 + sum1;

#pragma unroll
        for (int f = 0; f < 16; ++f) {
            o[f][0] *= cr0; o[f][1] *= cr0;
            o[f][2] *= cr1; o[f][3] *= cr1;
        }

        // P -> smem (fp16); same warp reads back its own rows only
#pragma unroll
        for (int j = 0; j < 8; ++j) {
            *(__half2*)(smh + OFF_PS + (qr + r) * VSH + j * 8 + 2 * c4) =
                __floats2half2_rn(s[j][0], s[j][1]);
            *(__half2*)(smh + OFF_PS + (qr + r + 8) * VSH + j * 8 + 2 * c4) =
                __floats2half2_rn(s[j][2], s[j][3]);
        }
        __syncwarp();

        // O += P V
#pragma unroll
        for (int kk = 0; kk < AK; kk += 16) {
            uint32_t a[4];
            ldm_x4(a, ps_a + ((qr + aRow) * VSH + kk + aCol) * 2);
#pragma unroll
            for (int fp = 0; fp < 8; ++fp) {
                uint32_t bb[4];
                ldm_x4(bb, vt_a + ((fp * 16 + bRow) * VSH + kk + bCol) * 2);
                mma_h(o[2 * fp],     a, bb[0], bb[1]);
                mma_h(o[2 * fp + 1], a, bb[2], bb[3]);
            }
        }
    }

    // epilogue
    float inv0 = 1.f / l_run[0];
    float inv1 = 1.f / l_run[1];
#pragma unroll
    for (int f = 0; f < 16; ++f) {
        long base0 = (long)row0 * QD + h * HD + f * 8 + 2 * c4;
        *(__half2*)&gctx[base0] =
            __floats2half2_rn(o[f][0] * inv0, o[f][1] * inv0);
        *(__half2*)&gctx[base0 + 8L * QD] =
            __floats2half2_rn(o[f][2] * inv1, o[f][3] * inv1);
    }
}

// ---------------------------------------------------------------------------
extern "C" void kernel_launch(void* const* d_in, const int* in_sizes, int n_in,
                              void* d_out, int out_size) {
    const float* hidden = (const float*)d_in[0];
    const float* Wq = (const float*)d_in[3];
    const float* Wk = (const float*)d_in[4];
    const float* Wv = (const float*)d_in[5];
    const float* Wo = (const float*)d_in[6];
    const float* qw = (const float*)d_in[7];
    const float* kw = (const float*)d_in[8];
    float* out = (float*)d_out;

    float *pqkv;
    __half *phid, *pw1, *pwo, *pqh, *pkh, *pvt, *pctx;
    cudaGetSymbolAddress((void**)&pqkv, g_qkv);
    cudaGetSymbolAddress((void**)&phid, g_hid_h);
    cudaGetSymbolAddress((void**)&pw1, g_w1_h);
    cudaGetSymbolAddress((void**)&pwo, g_wo_h);
    cudaGetSymbolAddress((void**)&pqh, g_q_h);
    cudaGetSymbolAddress((void**)&pkh, g_k_h);
    cudaGetSymbolAddress((void**)&pvt, g_vt);
    cudaGetSymbolAddress((void**)&pctx, g_ctx_h);

    // fp32 -> fp16 rounding; weights packed [Wq|Wk|Wv]
    round_h_kernel<<<(SEQ*HIDDEN)/2048, 256>>>(phid, hidden);
    round_h_kernel<<<(QD*HIDDEN)/2048, 256>>>(pw1, Wq);
    round_h_kernel<<<(1024*HIDDEN)/2048, 256>>>(pw1 + (long)4096*HIDDEN, Wk);
    round_h_kernel<<<(1024*HIDDEN)/2048, 256>>>(pw1 + (long)5120*HIDDEN, Wv);
    round_h_kernel<<<(HIDDEN*QD)/2048, 256>>>(pwo, Wo);

    cudaFuncSetAttribute(hgemm, cudaFuncAttributeMaxDynamicSharedMemorySize,
                         GEMM_SMEM_BYTES);

    // Fused QKV projection
    hgemm<<<dim3(N1 / 128, SEQ / 128), 256, GEMM_SMEM_BYTES>>>(phid, pw1, pqkv, N1, HIDDEN);

    // RMSNorm + RoPE (Q scaled) + V transpose
    norm_rope_kernel<<<dim3(SEQ, NH + NKV), 128>>>(pqkv, pqh, pkh, qw, kw);
    vtrans_kernel<<<dim3(SEQ / 32, 1024 / 32), 256>>>(pqkv, pvt);

    cudaFuncSetAttribute(attn_mma, cudaFuncAttributeMaxDynamicSharedMemorySize,
                         ATTN_SMEM_BYTES);
    attn_mma<<<dim3(SEQ / AQ, NH), 256, ATTN_SMEM_BYTES>>>(pqh, pkh, pvt, pctx);

    // Output projection -> d_out
    hgemm<<<dim3(HIDDEN / 128, SEQ / 128), 256, GEMM_SMEM_BYTES>>>(pctx, pwo, out, HIDDEN, HIDDEN);
}

// round 10
// speedup vs baseline: 7.9580x; 1.0380x over previous
#include <cuda_runtime.h>
#include <cuda_fp16.h>
#include <math.h>
#include <stdint.h>

#define SEQ 2048
#define HIDDEN 4096
#define NH 32
#define NKV 8
#define HD 128
#define QD (NH*HD)     // 4096
#define N1 6144        // fused Q|K|V output width

// Scratch (static device globals)
__device__ float  g_qkv[SEQ*N1];
__device__ __half g_hid_h[SEQ*HIDDEN];
__device__ __half g_w1_h[N1*HIDDEN];      // [Wq | Wk | Wv] rows
__device__ __half g_wo_h[HIDDEN*QD];
__device__ __half g_q_h[SEQ*QD];          // normed+roped+scaled Q
__device__ __half g_k_h[SEQ*1024];        // normed+roped K
__device__ __half g_vt[1024*SEQ];         // V^T: [kvh*128+d][token]
__device__ __half g_ctx_h[SEQ*QD];

__device__ __forceinline__ void ldm_x4(uint32_t* r, uint32_t addr) {
    asm volatile("ldmatrix.sync.aligned.m8n8.x4.shared.b16 {%0,%1,%2,%3}, [%4];"
        : "=r"(r[0]), "=r"(r[1]), "=r"(r[2]), "=r"(r[3]) : "r"(addr));
}

__device__ __forceinline__ void mma_h(float* d, const uint32_t* a,
                                      uint32_t b0, uint32_t b1) {
    asm volatile(
        "mma.sync.aligned.m16n8k16.row.col.f32.f16.f16.f32 "
        "{%0,%1,%2,%3},{%4,%5,%6,%7},{%8,%9},{%0,%1,%2,%3};\n"
        : "+f"(d[0]), "+f"(d[1]), "+f"(d[2]), "+f"(d[3])
        : "r"(a[0]), "r"(a[1]), "r"(a[2]), "r"(a[3]), "r"(b0), "r"(b1));
}

// ---------------------------------------------------------------------------
// Merged fp32->fp16 rounding: one launch for hid/Wq/Wk/Wv/Wo.
// Block = 2048 elements (256 thr x 8). Ranges: 4096|8192|2048|2048|8192.
// ---------------------------------------------------------------------------
__global__ void __launch_bounds__(256) round_all(
        __half* __restrict__ hid, const float* __restrict__ shid,
        __half* __restrict__ w1,  const float* __restrict__ wq,
        const float* __restrict__ wk, const float* __restrict__ wv,
        __half* __restrict__ wo,  const float* __restrict__ swo) {
    long b = blockIdx.x;
    const float* src; __half* dst; long off;
    if (b < 4096)        { src = shid; dst = hid;               off = b; }
    else if (b < 12288)  { src = wq;   dst = w1;                off = b - 4096; }
    else if (b < 14336)  { src = wk;   dst = w1 + 16777216L;    off = b - 12288; }
    else if (b < 16384)  { src = wv;   dst = w1 + 20971520L;    off = b - 14336; }
    else                 { src = swo;  dst = wo;                off = b - 16384; }
    long i = off * 2048 + (long)threadIdx.x * 8;
    float4 v0 = *(const float4*)(src + i);
    float4 v1 = *(const float4*)(src + i + 4);
    __half2 h[4];
    h[0] = __floats2half2_rn(v0.x, v0.y);
    h[1] = __floats2half2_rn(v0.z, v0.w);
    h[2] = __floats2half2_rn(v1.x, v1.y);
    h[3] = __floats2half2_rn(v1.z, v1.w);
    *(uint4*)(dst + i) = *(uint4*)h;
}

// ---------------------------------------------------------------------------
// fp16 GEMM: C[m,n] = sum_k A[m*K+k]*B[n*K+k], fp32 accum.
// 128x128 tile, BK=64, 256 threads, 3-stage cp.async, ONE barrier per iter,
// 2 CTAs/SM.
// ---------------------------------------------------------------------------
#define SA_H 72
#define STG_OP_BYTES (128*SA_H*2)
#define STAGE_BYTES (2*STG_OP_BYTES)
#define NST 3
#define GEMM_SMEM_BYTES (NST*STAGE_BYTES)

__global__ void __launch_bounds__(256, 2) hgemm(const __half* __restrict__ A,
                                                const __half* __restrict__ B,
                                                float* __restrict__ C,
                                                int N, int K) {
    extern __shared__ char smraw[];
    uint32_t sbase = (uint32_t)__cvta_generic_to_shared(smraw);
    const int tid = threadIdx.x;
    const int lane = tid & 31;
    const int warp = tid >> 5;
    const int wm = (warp & 3) * 32;
    const int wn = (warp >> 2) * 64;
    const int m0 = blockIdx.y * 128, n0 = blockIdx.x * 128;

    float acc[2][8][4];
#pragma unroll
    for (int i = 0; i < 2; ++i)
#pragma unroll
        for (int j = 0; j < 8; ++j)
#pragma unroll
            for (int x = 0; x < 4; ++x) acc[i][j][x] = 0.f;

    const int nk = K >> 6;

    auto prefetch = [&](int t) {
        int slot = t % NST;
        uint32_t sa = sbase + slot * STAGE_BYTES;
        uint32_t sb = sa + STG_OP_BYTES;
        int k0 = t << 6;
#pragma unroll
        for (int i = 0; i < 4; ++i) {
            int c = tid + i * 256;
            int row = c >> 3, cc = c & 7;
            uint32_t da = sa + row * 144 + cc * 16;
            const __half* ga = A + (long)(m0 + row) * K + k0 + cc * 8;
            asm volatile("cp.async.cg.shared.global [%0], [%1], 16;\n" :: "r"(da), "l"(ga));
            uint32_t db = sb + row * 144 + cc * 16;
            const __half* gb = B + (long)(n0 + row) * K + k0 + cc * 8;
            asm volatile("cp.async.cg.shared.global [%0], [%1], 16;\n" :: "r"(db), "l"(gb));
        }
        asm volatile("cp.async.commit_group;\n");
    };

    prefetch(0);
    prefetch(1);

    const int aRow = lane & 15;
    const int aCol = 8 * (lane >> 4);
    const int bRow = (lane & 7) + ((lane >> 4) & 1) * 8;
    const int bCol = ((lane >> 3) & 1) * 8;

    for (int t = 0; t < nk; ++t) {
        asm volatile("cp.async.wait_group 1;\n");   // group t complete
        __syncthreads();                             // visibility + WAR guard
        if (t + 2 < nk) prefetch(t + 2);             // slot (t+2)%3: safe
        else asm volatile("cp.async.commit_group;\n");  // uniform accounting

        uint32_t sa = sbase + (t % NST) * STAGE_BYTES;
        uint32_t sb = sa + STG_OP_BYTES;

#pragma unroll
        for (int kk = 0; kk < 64; kk += 16) {
            uint32_t a[2][4];
#pragma unroll
            for (int i = 0; i < 2; ++i)
                ldm_x4(a[i], sa + ((wm + i * 16 + aRow) * SA_H + kk + aCol) * 2);
            uint32_t b[8][2];
#pragma unroll
            for (int jp = 0; jp < 4; ++jp) {
                uint32_t bb[4];
                ldm_x4(bb, sb + ((wn + jp * 16 + bRow) * SA_H + kk + bCol) * 2);
                b[2 * jp][0] = bb[0]; b[2 * jp][1] = bb[1];
                b[2 * jp + 1][0] = bb[2]; b[2 * jp + 1][1] = bb[3];
            }
#pragma unroll
            for (int i = 0; i < 2; ++i)
#pragma unroll
                for (int j = 0; j < 8; ++j)
                    mma_h(acc[i][j], a[i], b[j][0], b[j][1]);
        }
    }

    const int r = lane >> 2, c2 = (lane & 3) * 2;
#pragma unroll
    for (int i = 0; i < 2; ++i)
#pragma unroll
        for (int j = 0; j < 8; ++j) {
            long row0 = m0 + wm + i * 16 + r;
            long col = n0 + wn + j * 8 + c2;
            *(float2*)&C[row0 * N + col]       = make_float2(acc[i][j][0], acc[i][j][1]);
            *(float2*)&C[(row0 + 8) * N + col] = make_float2(acc[i][j][2], acc[i][j][3]);
        }
}

// ---------------------------------------------------------------------------
// RMSNorm + RoPE from fused QKV buffer; writes fp16 (Q pre-scaled).
// ---------------------------------------------------------------------------
__global__ void __launch_bounds__(128) norm_rope_kernel(const float* __restrict__ qkv,
                                                        __half* __restrict__ qh,
                                                        __half* __restrict__ kh,
                                                        const float* __restrict__ qw,
                                                        const float* __restrict__ kw) {
    const int s = blockIdx.x;
    const int hy = blockIdx.y;
    const int t = threadIdx.x;
    const bool isq = hy < NH;
    const float* src = qkv + (long)s * N1 + (isq ? hy * HD : HIDDEN + (hy - NH) * HD);
    const float* w = isq ? qw : kw;

    float x = src[t];
    float v = x * x;
#pragma unroll
    for (int off = 16; off; off >>= 1) v += __shfl_xor_sync(0xffffffffu, v, off);

    __shared__ float ws[4];
    __shared__ float xs[128];
    if ((t & 31) == 0) ws[t >> 5] = v;
    __syncthreads();
    float var = (ws[0] + ws[1] + ws[2] + ws[3]) * (1.0f / 128.0f);
    float xn = x * rsqrtf(var + 1e-6f) * w[t];
    xs[t] = xn;
    __syncthreads();

    const int half = t & 63;
    float invf = exp2f(-19.931568569324174f * ((float)half * (1.0f / 64.0f)));
    float ang = (float)s * invf;
    float c = cosf(ang), sn = sinf(ang);
    float rot = (t < 64) ? -xs[t + 64] : xs[t - 64];
    float y = xn * c + rot * sn;

    if (isq)
        qh[(long)s * QD + hy * HD + t] = __float2half_rn(y * 0.08838834764831845f);
    else
        kh[(long)s * 1024 + (hy - NH) * HD + t] = __float2half_rn(y);
}

// ---------------------------------------------------------------------------
// V transpose: qkv[s][5120+j] (fp32) -> vt[j][s] (fp16). 32x32 tiles.
// ---------------------------------------------------------------------------
__global__ void __launch_bounds__(256) vtrans_kernel(const float* __restrict__ qkv,
                                                     __half* __restrict__ vt) {
    __shared__ __half tile[32][33];
    const int s0 = blockIdx.x * 32, j0 = blockIdx.y * 32;
    const int tx = threadIdx.x & 31, ty = threadIdx.x >> 5;
#pragma unroll
    for (int yy = 0; yy < 4; ++yy) {
        int sr = ty + yy * 8;
        tile[sr][tx] = __float2half_rn(qkv[(long)(s0 + sr) * N1 + 5120 + j0 + tx]);
    }
    __syncthreads();
#pragma unroll
    for (int yy = 0; yy < 4; ++yy) {
        int jr = ty + yy * 8;
        vt[(long)(j0 + jr) * SEQ + s0 + tx] = tile[tx][jr];
    }
}

// ---------------------------------------------------------------------------
// Flash attention, fp16 mma. Q tile 128, KV tile 128 (double-buffered).
// Masking only in the final (diagonal) tile. 256 threads / 8 warps.
// ---------------------------------------------------------------------------
#define AQ 128
#define AK 128
#define QSH 136   // halves per row (272B)
// smem halves: Qs 128*136 | Ks[2] 128*136 | Vt[2] 128*136 | Ps 128*136
#define OFF_QS 0
#define OFF_KS 17408
#define OFF_VT (17408 + 2*17408)
#define OFF_PS (OFF_VT + 2*17408)
#define ATTN_SMEM_BYTES ((OFF_PS + 17408)*2)   // 208896

__global__ void __launch_bounds__(256) attn_mma(const __half* __restrict__ gq,
                                                const __half* __restrict__ gk,
                                                const __half* __restrict__ gvt,
                                                __half* __restrict__ gctx) {
    extern __shared__ __half smh[];
    uint32_t sb = (uint32_t)__cvta_generic_to_shared(smh);
    const uint32_t qs_a = sb + OFF_QS * 2;
    const uint32_t ps_a = sb + OFF_PS * 2;

    const int tid = threadIdx.x;
    const int lane = tid & 31;
    const int warp = tid >> 5;
    const int r = lane >> 2, c4 = lane & 3;
    const int qblk = gridDim.x - 1 - blockIdx.x;   // heavy blocks first
    const int q0 = qblk * AQ;
    const int h = blockIdx.y;
    const int kvh = h >> 2;
    const int qr = warp * 16;

    const int aRow = lane & 15;
    const int aCol = 8 * (lane >> 4);
    const int bRow = (lane & 7) + ((lane >> 4) & 1) * 8;
    const int bCol = ((lane >> 3) & 1) * 8;

    const int ntiles = qblk + 1;

    auto fill = [&](int t) {
        int slot = t & 1;
        int k0 = t * AK;
        uint32_t ka = sb + (OFF_KS + slot * 17408) * 2;
        uint32_t va = sb + (OFF_VT + slot * 17408) * 2;
#pragma unroll
        for (int i = 0; i < 8; ++i) {               // K: 128 rows x 16 chunks
            int idx = tid + i * 256;
            int row = idx >> 4, cc = idx & 15;
            uint32_t dst = ka + row * 272 + cc * 16;
            const __half* src = gk + (long)(k0 + row) * 1024 + kvh * HD + cc * 8;
            asm volatile("cp.async.cg.shared.global [%0], [%1], 16;\n" :: "r"(dst), "l"(src));
        }
#pragma unroll
        for (int i = 0; i < 8; ++i) {               // V^T: 128 rows x 16 chunks
            int idx = tid + i * 256;
            int row = idx >> 4, cc = idx & 15;
            uint32_t dst = va + row * 272 + cc * 16;
            const __half* src = gvt + (long)(kvh * HD + row) * SEQ + k0 + cc * 8;
            asm volatile("cp.async.cg.shared.global [%0], [%1], 16;\n" :: "r"(dst), "l"(src));
        }
        asm volatile("cp.async.commit_group;\n");
    };

    fill(0);

    // Q tile (pre-scaled fp16)
#pragma unroll
    for (int i = 0; i < 8; ++i) {
        int idx = tid + i * 256;
        int row = idx >> 4, cc = idx & 15;
        *(uint4*)(smh + OFF_QS + row * QSH + cc * 8) =
            *(const uint4*)(gq + (long)(q0 + row) * QD + h * HD + cc * 8);
    }

    float m_run[2] = {-1e30f, -1e30f};
    float l_run[2] = {0.f, 0.f};
    float o[16][4];
#pragma unroll
    for (int f = 0; f < 16; ++f)
#pragma unroll
        for (int x = 0; x < 4; ++x) o[f][x] = 0.f;

    const int row0 = q0 + qr + r;
    const int row1 = row0 + 8;

    for (int t = 0; t < ntiles; ++t) {
        const int k0 = t * AK;
        __syncthreads();                            // prev readers of slot (t+1)&1 done
        if (t + 1 < ntiles) {
            fill(t + 1);
            asm volatile("cp.async.wait_group 1;\n");
        } else {
            asm volatile("cp.async.wait_group 0;\n");
        }
        __syncthreads();                            // tile t visible

        const uint32_t ks_a = sb + (OFF_KS + (t & 1) * 17408) * 2;
        const uint32_t vt_a = sb + (OFF_VT + (t & 1) * 17408) * 2;

        // S = Q K^T : 16x128 per warp
        float s[16][4];
#pragma unroll
        for (int j = 0; j < 16; ++j)
#pragma unroll
            for (int x = 0; x < 4; ++x) s[j][x] = 0.f;

#pragma unroll
        for (int kk = 0; kk < HD; kk += 16) {
            uint32_t a[4];
            ldm_x4(a, qs_a + ((qr + aRow) * QSH + kk + aCol) * 2);
#pragma unroll
            for (int jp = 0; jp < 8; ++jp) {
                uint32_t bb[4];
                ldm_x4(bb, ks_a + ((jp * 16 + bRow) * QSH + kk + bCol) * 2);
                mma_h(s[2 * jp],     a, bb[0], bb[1]);
                mma_h(s[2 * jp + 1], a, bb[2], bb[3]);
            }
        }

        // online softmax (mask only diagonal tile)
        const bool dg = (t == ntiles - 1);
        float mx0 = -1e30f, mx1 = -1e30f;
#pragma unroll
        for (int j = 0; j < 16; ++j) {
            int col = k0 + j * 8 + 2 * c4;
            if (dg) {
                if (col     > row0) s[j][0] = -1e30f;
                if (col + 1 > row0) s[j][1] = -1e30f;
                if (col     > row1) s[j][2] = -1e30f;
                if (col + 1 > row1) s[j][3] = -1e30f;
            }
            mx0 = fmaxf(mx0, fmaxf(s[j][0], s[j][1]));
            mx1 = fmaxf(mx1, fmaxf(s[j][2], s[j][3]));
        }
        mx0 = fmaxf(mx0, __shfl_xor_sync(0xffffffffu, mx0, 1));
        mx0 = fmaxf(mx0, __shfl_xor_sync(0xffffffffu, mx0, 2));
        mx1 = fmaxf(mx1, __shfl_xor_sync(0xffffffffu, mx1, 1));
        mx1 = fmaxf(mx1, __shfl_xor_sync(0xffffffffu, mx1, 2));

        float mn0 = fmaxf(m_run[0], mx0);
        float mn1 = fmaxf(m_run[1], mx1);
        float cr0 = __expf(m_run[0] - mn0);
        float cr1 = __expf(m_run[1] - mn1);
        m_run[0] = mn0; m_run[1] = mn1;

        float sum0 = 0.f, sum1 = 0.f;
#pragma unroll
        for (int j = 0; j < 16; ++j) {
            s[j][0] = __expf(s[j][0] - mn0);
            s[j][1] = __expf(s[j][1] - mn0);
            s[j][2] = __expf(s[j][2] - mn1);
            s[j][3] = __expf(s[j][3] - mn1);
            sum0 += s[j][0] + s[j][1];
            sum1 += s[j][2] + s[j][3];
        }
        sum0 += __shfl_xor_sync(0xffffffffu, sum0, 1);
        sum0 += __shfl_xor_sync(0xffffffffu, sum0, 2);
        sum1 += __shfl_xor_sync(0xffffffffu, sum1, 1);
        sum1 += __shfl_xor_sync(0xffffffffu, sum1, 2);
        l_run[0] = l_run[0] * cr0 + sum0;
        l_run[1] = l_run[1] * cr1 + sum1;

#pragma unroll
        for (int f = 0; f < 16; ++f) {
            o[f][0] *= cr0; o[f][1] *= cr0;
            o[f][2] *= cr1; o[f][3] *= cr1;
        }

        // P -> smem (fp16); warp-private rows
#pragma unroll
        for (int j = 0; j < 16; ++j) {
            *(__half2*)(smh + OFF_PS + (qr + r) * QSH + j * 8 + 2 * c4) =
                __floats2half2_rn(s[j][0], s[j][1]);
            *(__half2*)(smh + OFF_PS + (qr + r + 8) * QSH + j * 8 + 2 * c4) =
                __floats2half2_rn(s[j][2], s[j][3]);
        }
        __syncwarp();

        // O += P V
#pragma unroll
        for (int kk = 0; kk < AK; kk += 16) {
            uint32_t a[4];
            ldm_x4(a, ps_a + ((qr + aRow) * QSH + kk + aCol) * 2);
#pragma unroll
            for (int fp = 0; fp < 8; ++fp) {
                uint32_t bb[4];
                ldm_x4(bb, vt_a + ((fp * 16 + bRow) * QSH + kk + bCol) * 2);
                mma_h(o[2 * fp],     a, bb[0], bb[1]);
                mma_h(o[2 * fp + 1], a, bb[2], bb[3]);
            }
        }
    }

    float inv0 = 1.f / l_run[0];
    float inv1 = 1.f / l_run[1];
#pragma unroll
    for (int f = 0; f < 16; ++f) {
        long base0 = (long)row0 * QD + h * HD + f * 8 + 2 * c4;
        *(__half2*)&gctx[base0] =
            __floats2half2_rn(o[f][0] * inv0, o[f][1] * inv0);
        *(__half2*)&gctx[base0 + 8L * QD] =
            __floats2half2_rn(o[f][2] * inv1, o[f][3] * inv1);
    }
}

// ---------------------------------------------------------------------------
extern "C" void kernel_launch(void* const* d_in, const int* in_sizes, int n_in,
                              void* d_out, int out_size) {
    const float* hidden = (const float*)d_in[0];
    const float* Wq = (const float*)d_in[3];
    const float* Wk = (const float*)d_in[4];
    const float* Wv = (const float*)d_in[5];
    const float* Wo = (const float*)d_in[6];
    const float* qw = (const float*)d_in[7];
    const float* kw = (const float*)d_in[8];
    float* out = (float*)d_out;

    float *pqkv;
    __half *phid, *pw1, *pwo, *pqh, *pkh, *pvt, *pctx;
    cudaGetSymbolAddress((void**)&pqkv, g_qkv);
    cudaGetSymbolAddress((void**)&phid, g_hid_h);
    cudaGetSymbolAddress((void**)&pw1, g_w1_h);
    cudaGetSymbolAddress((void**)&pwo, g_wo_h);
    cudaGetSymbolAddress((void**)&pqh, g_q_h);
    cudaGetSymbolAddress((void**)&pkh, g_k_h);
    cudaGetSymbolAddress((void**)&pvt, g_vt);
    cudaGetSymbolAddress((void**)&pctx, g_ctx_h);

    // One merged rounding launch (hid | Wq | Wk | Wv | Wo)
    round_all<<<24576, 256>>>(phid, hidden, pw1, Wq, Wk, Wv, pwo, Wo);

    cudaFuncSetAttribute(hgemm, cudaFuncAttributeMaxDynamicSharedMemorySize,
                         GEMM_SMEM_BYTES);

    // Fused QKV projection
    hgemm<<<dim3(N1 / 128, SEQ / 128), 256, GEMM_SMEM_BYTES>>>(phid, pw1, pqkv, N1, HIDDEN);

    // RMSNorm + RoPE (Q scaled) + V transpose
    norm_rope_kernel<<<dim3(SEQ, NH + NKV), 128>>>(pqkv, pqh, pkh, qw, kw);
    vtrans_kernel<<<dim3(SEQ / 32, 1024 / 32), 256>>>(pqkv, pvt);

    cudaFuncSetAttribute(attn_mma, cudaFuncAttributeMaxDynamicSharedMemorySize,
                         ATTN_SMEM_BYTES);
    attn_mma<<<dim3(SEQ / AQ, NH), 256, ATTN_SMEM_BYTES>>>(pqh, pkh, pvt, pctx);

    // Output projection -> d_out
    hgemm<<<dim3(HIDDEN / 128, SEQ / 128), 256, GEMM_SMEM_BYTES>>>(pctx, pwo, out, HIDDEN, HIDDEN);
}

// round 11
// speedup vs baseline: 8.3748x; 1.0524x over previous
#include <cuda_runtime.h>
#include <cuda_fp16.h>
#include <math.h>
#include <stdint.h>

#define SEQ 2048
#define HIDDEN 4096
#define NH 32
#define NKV 8
#define HD 128
#define QD (NH*HD)     // 4096
#define N1 6144        // fused Q|K|V output width

// Scratch (static device globals)
__device__ __half g_hid_h[SEQ*HIDDEN];
__device__ __half g_w1_h[N1*HIDDEN];      // [Wq | Wk | Wv] rows
__device__ __half g_wo_h[HIDDEN*QD];
__device__ __half g_q_h[SEQ*QD];          // normed+roped+scaled Q
__device__ __half g_k_h[SEQ*1024];        // normed+roped K
__device__ __half g_v_h[SEQ*1024];        // V (fp16, token-major)
__device__ __half g_vt[1024*SEQ];         // V^T: [kvh*128+d][token]
__device__ __half g_ctx_h[SEQ*QD];
__device__ float2 g_cs[SEQ*64];           // (cos, sin) per (token, freq)

__device__ __forceinline__ void ldm_x4(uint32_t* r, uint32_t addr) {
    asm volatile("ldmatrix.sync.aligned.m8n8.x4.shared.b16 {%0,%1,%2,%3}, [%4];"
        : "=r"(r[0]), "=r"(r[1]), "=r"(r[2]), "=r"(r[3]) : "r"(addr));
}

__device__ __forceinline__ void mma_h(float* d, const uint32_t* a,
                                      uint32_t b0, uint32_t b1) {
    asm volatile(
        "mma.sync.aligned.m16n8k16.row.col.f32.f16.f16.f32 "
        "{%0,%1,%2,%3},{%4,%5,%6,%7},{%8,%9},{%0,%1,%2,%3};\n"
        : "+f"(d[0]), "+f"(d[1]), "+f"(d[2]), "+f"(d[3])
        : "r"(a[0]), "r"(a[1]), "r"(a[2]), "r"(a[3]), "r"(b0), "r"(b1));
}

// ---------------------------------------------------------------------------
// cos/sin table: g_cs[s][f] = (cos(s*invf), sin(s*invf)), f = 0..63
// ---------------------------------------------------------------------------
__global__ void __launch_bounds__(64) cs_table_kernel(float2* __restrict__ cs) {
    int s = blockIdx.x, f = threadIdx.x;
    float invf = exp2f(-19.931568569324174f * ((float)f * (1.0f / 64.0f)));
    float ang = (float)s * invf;
    cs[s * 64 + f] = make_float2(cosf(ang), sinf(ang));
}

// ---------------------------------------------------------------------------
// Merged fp32->fp16 rounding, 16 elems/thread (4 indep float4 loads).
// Block = 4096 elements. Ranges: hid 2048 | Wq 4096 | Wk 1024 | Wv 1024 | Wo 4096.
// ---------------------------------------------------------------------------
__global__ void __launch_bounds__(256) round_all(
        __half* __restrict__ hid, const float* __restrict__ shid,
        __half* __restrict__ w1,  const float* __restrict__ wq,
        const float* __restrict__ wk, const float* __restrict__ wv,
        __half* __restrict__ wo,  const float* __restrict__ swo) {
    long b = blockIdx.x;
    const float* src; __half* dst; long off;
    if (b < 2048)       { src = shid; dst = hid;            off = b; }
    else if (b < 6144)  { src = wq;   dst = w1;             off = b - 2048; }
    else if (b < 7168)  { src = wk;   dst = w1 + 16777216L; off = b - 6144; }
    else if (b < 8192)  { src = wv;   dst = w1 + 20971520L; off = b - 7168; }
    else                { src = swo;  dst = wo;             off = b - 8192; }
    long i = off * 4096 + (long)threadIdx.x * 16;
    float4 v0 = *(const float4*)(src + i);
    float4 v1 = *(const float4*)(src + i + 4);
    float4 v2 = *(const float4*)(src + i + 8);
    float4 v3 = *(const float4*)(src + i + 12);
    __half2 h[8];
    h[0] = __floats2half2_rn(v0.x, v0.y); h[1] = __floats2half2_rn(v0.z, v0.w);
    h[2] = __floats2half2_rn(v1.x, v1.y); h[3] = __floats2half2_rn(v1.z, v1.w);
    h[4] = __floats2half2_rn(v2.x, v2.y); h[5] = __floats2half2_rn(v2.z, v2.w);
    h[6] = __floats2half2_rn(v3.x, v3.y); h[7] = __floats2half2_rn(v3.z, v3.w);
    *(uint4*)(dst + i)     = *(uint4*)h;
    *(uint4*)(dst + i + 8) = *(uint4*)(h + 4);
}

// ---------------------------------------------------------------------------
// fp16 GEMM, 128x128 tile, BK=64, 3-stage cp.async, 2 CTAs/SM.
// mode 0: plain fp32 C store.  mode 1: fused QKV epilogue:
//   n0 <  4096 : Q head  -> RMSNorm + RoPE + 1/sqrt(128) scale -> g_q_h fp16
//   n0 <  5120 : K head  -> RMSNorm + RoPE -> g_k_h fp16
//   else       : V head  -> plain fp16 -> g_v_h
// ---------------------------------------------------------------------------
#define SA_H 72
#define STG_OP_BYTES (128*SA_H*2)
#define STAGE_BYTES (2*STG_OP_BYTES)
#define NST 3
#define GEMM_SMEM_BYTES (NST*STAGE_BYTES)

__global__ void __launch_bounds__(256, 2) hgemm(const __half* __restrict__ A,
                                                const __half* __restrict__ B,
                                                float* __restrict__ C,
                                                int N, int K, int mode,
                                                __half* __restrict__ qh,
                                                __half* __restrict__ kh,
                                                __half* __restrict__ vh,
                                                const float* __restrict__ qw,
                                                const float* __restrict__ kw,
                                                const float2* __restrict__ cs) {
    extern __shared__ char smraw[];
    uint32_t sbase = (uint32_t)__cvta_generic_to_shared(smraw);
    const int tid = threadIdx.x;
    const int lane = tid & 31;
    const int warp = tid >> 5;
    const int wm = (warp & 3) * 32;
    const int wn = (warp >> 2) * 64;
    const int m0 = blockIdx.y * 128, n0 = blockIdx.x * 128;

    float acc[2][8][4];
#pragma unroll
    for (int i = 0; i < 2; ++i)
#pragma unroll
        for (int j = 0; j < 8; ++j)
#pragma unroll
            for (int x = 0; x < 4; ++x) acc[i][j][x] = 0.f;

    const int nk = K >> 6;

    auto prefetch = [&](int t) {
        int slot = t % NST;
        uint32_t sa = sbase + slot * STAGE_BYTES;
        uint32_t sb = sa + STG_OP_BYTES;
        int k0 = t << 6;
#pragma unroll
        for (int i = 0; i < 4; ++i) {
            int c = tid + i * 256;
            int row = c >> 3, cc = c & 7;
            uint32_t da = sa + row * 144 + cc * 16;
            const __half* ga = A + (long)(m0 + row) * K + k0 + cc * 8;
            asm volatile("cp.async.cg.shared.global [%0], [%1], 16;\n" :: "r"(da), "l"(ga));
            uint32_t db = sb + row * 144 + cc * 16;
            const __half* gb = B + (long)(n0 + row) * K + k0 + cc * 8;
            asm volatile("cp.async.cg.shared.global [%0], [%1], 16;\n" :: "r"(db), "l"(gb));
        }
        asm volatile("cp.async.commit_group;\n");
    };

    prefetch(0);
    prefetch(1);

    const int aRow = lane & 15;
    const int aCol = 8 * (lane >> 4);
    const int bRow = (lane & 7) + ((lane >> 4) & 1) * 8;
    const int bCol = ((lane >> 3) & 1) * 8;

    for (int t = 0; t < nk; ++t) {
        asm volatile("cp.async.wait_group 1;\n");
        __syncthreads();
        if (t + 2 < nk) prefetch(t + 2);
        else asm volatile("cp.async.commit_group;\n");

        uint32_t sa = sbase + (t % NST) * STAGE_BYTES;
        uint32_t sb = sa + STG_OP_BYTES;

#pragma unroll
        for (int kk = 0; kk < 64; kk += 16) {
            uint32_t a[2][4];
#pragma unroll
            for (int i = 0; i < 2; ++i)
                ldm_x4(a[i], sa + ((wm + i * 16 + aRow) * SA_H + kk + aCol) * 2);
            uint32_t b[8][2];
#pragma unroll
            for (int jp = 0; jp < 4; ++jp) {
                uint32_t bb[4];
                ldm_x4(bb, sb + ((wn + jp * 16 + bRow) * SA_H + kk + bCol) * 2);
                b[2 * jp][0] = bb[0]; b[2 * jp][1] = bb[1];
                b[2 * jp + 1][0] = bb[2]; b[2 * jp + 1][1] = bb[3];
            }
#pragma unroll
            for (int i = 0; i < 2; ++i)
#pragma unroll
                for (int j = 0; j < 8; ++j)
                    mma_h(acc[i][j], a[i], b[j][0], b[j][1]);
        }
    }

    const int r = lane >> 2, c2 = (lane & 3) * 2;

    if (mode == 0) {
#pragma unroll
        for (int i = 0; i < 2; ++i)
#pragma unroll
            for (int j = 0; j < 8; ++j) {
                long row0 = m0 + wm + i * 16 + r;
                long col = n0 + wn + j * 8 + c2;
                *(float2*)&C[row0 * N + col]       = make_float2(acc[i][j][0], acc[i][j][1]);
                *(float2*)&C[(row0 + 8) * N + col] = make_float2(acc[i][j][2], acc[i][j][3]);
            }
        return;
    }

    // ---- mode 1: fused QKV epilogue ----
    if (n0 >= 5120) {
        // V: plain fp16 store, token-major
#pragma unroll
        for (int i = 0; i < 2; ++i)
#pragma unroll
            for (int j = 0; j < 8; ++j) {
                long row0 = m0 + wm + i * 16 + r;
                long col = (n0 - 5120) + wn + j * 8 + c2;
                *(__half2*)&vh[row0 * 1024 + col] =
                    __floats2half2_rn(acc[i][j][0], acc[i][j][1]);
                *(__half2*)&vh[(row0 + 8) * 1024 + col] =
                    __floats2half2_rn(acc[i][j][2], acc[i][j][3]);
            }
        return;
    }

    // Q or K: RMSNorm over the 128-col head + RoPE
    float* Sm = (float*)smraw;            // [128][132]
    float* part = Sm + 128 * 132;         // [128][2]
    float* rs = part + 256;               // [128]

    __syncthreads();                      // mainloop smem reads done (all warps)

    float psum[4] = {0.f, 0.f, 0.f, 0.f};
#pragma unroll
    for (int i = 0; i < 2; ++i)
#pragma unroll
        for (int j = 0; j < 8; ++j) {
            int row_a = wm + i * 16 + r;
            int col = wn + j * 8 + c2;
            float a0 = acc[i][j][0], a1 = acc[i][j][1];
            float a2 = acc[i][j][2], a3 = acc[i][j][3];
            *(float2*)&Sm[row_a * 132 + col]       = make_float2(a0, a1);
            *(float2*)&Sm[(row_a + 8) * 132 + col] = make_float2(a2, a3);
            psum[i * 2 + 0] += a0 * a0 + a1 * a1;
            psum[i * 2 + 1] += a2 * a2 + a3 * a3;
        }
#pragma unroll
    for (int k = 0; k < 4; ++k) {
        psum[k] += __shfl_xor_sync(0xffffffffu, psum[k], 1);
        psum[k] += __shfl_xor_sync(0xffffffffu, psum[k], 2);
    }
    if ((lane & 3) == 0) {
        int hfl = warp >> 2;
        part[(wm + r) * 2 + hfl]        = psum[0];
        part[(wm + r + 8) * 2 + hfl]    = psum[1];
        part[(wm + 16 + r) * 2 + hfl]   = psum[2];
        part[(wm + 16 + r + 8) * 2 + hfl] = psum[3];
    }
    __syncthreads();
    if (tid < 128)
        rs[tid] = rsqrtf((part[tid * 2] + part[tid * 2 + 1]) * (1.0f / 128.0f) + 1e-6f);
    __syncthreads();

    const bool isQ = (n0 < 4096);
    const float* w = isQ ? qw : kw;
    __half* dst = isQ ? qh : kh;
    const long dstride = isQ ? 4096 : 1024;
    const long dcol0 = isQ ? n0 : (n0 - 4096);
    const float qs = isQ ? 0.08838834764831845f : 1.0f;

#pragma unroll
    for (int u = 0; u < 32; ++u) {
        int flat = tid + u * 256;          // 128 rows x 64 col-pairs
        int row = flat >> 6, cp = flat & 63;
        float rr = rs[row];
        float x1 = Sm[row * 132 + cp]      * rr * w[cp];
        float x2 = Sm[row * 132 + cp + 64] * rr * w[cp + 64];
        float2 csv = cs[(long)(m0 + row) * 64 + cp];
        float y1 = (x1 * csv.x - x2 * csv.y) * qs;
        float y2 = (x2 * csv.x + x1 * csv.y) * qs;
        long base = (long)(m0 + row) * dstride + dcol0;
        dst[base + cp]      = __float2half_rn(y1);
        dst[base + cp + 64] = __float2half_rn(y2);
    }
}

// ---------------------------------------------------------------------------
// V transpose: g_v_h[s][j] (fp16) -> g_vt[j][s]. 32x32 tiles.
// ---------------------------------------------------------------------------
__global__ void __launch_bounds__(256) vtrans_kernel(const __half* __restrict__ vh,
                                                     __half* __restrict__ vt) {
    __shared__ __half tile[32][33];
    const int s0 = blockIdx.x * 32, j0 = blockIdx.y * 32;
    const int tx = threadIdx.x & 31, ty = threadIdx.x >> 5;
#pragma unroll
    for (int yy = 0; yy < 4; ++yy) {
        int sr = ty + yy * 8;
        tile[sr][tx] = vh[(long)(s0 + sr) * 1024 + j0 + tx];
    }
    __syncthreads();
#pragma unroll
    for (int yy = 0; yy < 4; ++yy) {
        int jr = ty + yy * 8;
        vt[(long)(j0 + jr) * SEQ + s0 + tx] = tile[tx][jr];
    }
}

// ---------------------------------------------------------------------------
// Flash attention, fp16 mma. Q tile 128, KV tile 128 (double-buffered).
// ---------------------------------------------------------------------------
#define AQ 128
#define AK 128
#define QSH 136
#define OFF_QS 0
#define OFF_KS 17408
#define OFF_VT (17408 + 2*17408)
#define OFF_PS (OFF_VT + 2*17408)
#define ATTN_SMEM_BYTES ((OFF_PS + 17408)*2)

__global__ void __launch_bounds__(256) attn_mma(const __half* __restrict__ gq,
                                                const __half* __restrict__ gk,
                                                const __half* __restrict__ gvt,
                                                __half* __restrict__ gctx) {
    extern __shared__ __half smh[];
    uint32_t sb = (uint32_t)__cvta_generic_to_shared(smh);
    const uint32_t qs_a = sb + OFF_QS * 2;
    const uint32_t ps_a = sb + OFF_PS * 2;

    const int tid = threadIdx.x;
    const int lane = tid & 31;
    const int warp = tid >> 5;
    const int r = lane >> 2, c4 = lane & 3;
    const int qblk = gridDim.x - 1 - blockIdx.x;
    const int q0 = qblk * AQ;
    const int h = blockIdx.y;
    const int kvh = h >> 2;
    const int qr = warp * 16;

    const int aRow = lane & 15;
    const int aCol = 8 * (lane >> 4);
    const int bRow = (lane & 7) + ((lane >> 4) & 1) * 8;
    const int bCol = ((lane >> 3) & 1) * 8;

    const int ntiles = qblk + 1;

    auto fill = [&](int t) {
        int slot = t & 1;
        int k0 = t * AK;
        uint32_t ka = sb + (OFF_KS + slot * 17408) * 2;
        uint32_t va = sb + (OFF_VT + slot * 17408) * 2;
#pragma unroll
        for (int i = 0; i < 8; ++i) {
            int idx = tid + i * 256;
            int row = idx >> 4, cc = idx & 15;
            uint32_t dst = ka + row * 272 + cc * 16;
            const __half* src = gk + (long)(k0 + row) * 1024 + kvh * HD + cc * 8;
            asm volatile("cp.async.cg.shared.global [%0], [%1], 16;\n" :: "r"(dst), "l"(src));
        }
#pragma unroll
        for (int i = 0; i < 8; ++i) {
            int idx = tid + i * 256;
            int row = idx >> 4, cc = idx & 15;
            uint32_t dst = va + row * 272 + cc * 16;
            const __half* src = gvt + (long)(kvh * HD + row) * SEQ + k0 + cc * 8;
            asm volatile("cp.async.cg.shared.global [%0], [%1], 16;\n" :: "r"(dst), "l"(src));
        }
        asm volatile("cp.async.commit_group;\n");
    };

    fill(0);

#pragma unroll
    for (int i = 0; i < 8; ++i) {
        int idx = tid + i * 256;
        int row = idx >> 4, cc = idx & 15;
        *(uint4*)(smh + OFF_QS + row * QSH + cc * 8) =
            *(const uint4*)(gq + (long)(q0 + row) * QD + h * HD + cc * 8);
    }

    float m_run[2] = {-1e30f, -1e30f};
    float l_run[2] = {0.f, 0.f};
    float o[16][4];
#pragma unroll
    for (int f = 0; f < 16; ++f)
#pragma unroll
        for (int x = 0; x < 4; ++x) o[f][x] = 0.f;

    const int row0 = q0 + qr + r;
    const int row1 = row0 + 8;

    for (int t = 0; t < ntiles; ++t) {
        const int k0 = t * AK;
        __syncthreads();
        if (t + 1 < ntiles) {
            fill(t + 1);
            asm volatile("cp.async.wait_group 1;\n");
        } else {
            asm volatile("cp.async.wait_group 0;\n");
        }
        __syncthreads();

        const uint32_t ks_a = sb + (OFF_KS + (t & 1) * 17408) * 2;
        const uint32_t vt_a = sb + (OFF_VT + (t & 1) * 17408) * 2;

        float s[16][4];
#pragma unroll
        for (int j = 0; j < 16; ++j)
#pragma unroll
            for (int x = 0; x < 4; ++x) s[j][x] = 0.f;

#pragma unroll
        for (int kk = 0; kk < HD; kk += 16) {
            uint32_t a[4];
            ldm_x4(a, qs_a + ((qr + aRow) * QSH + kk + aCol) * 2);
#pragma unroll
            for (int jp = 0; jp < 8; ++jp) {
                uint32_t bb[4];
                ldm_x4(bb, ks_a + ((jp * 16 + bRow) * QSH + kk + bCol) * 2);
                mma_h(s[2 * jp],     a, bb[0], bb[1]);
                mma_h(s[2 * jp + 1], a, bb[2], bb[3]);
            }
        }

        const bool dg = (t == ntiles - 1);
        float mx0 = -1e30f, mx1 = -1e30f;
#pragma unroll
        for (int j = 0; j < 16; ++j) {
            int col = k0 + j * 8 + 2 * c4;
            if (dg) {
                if (col     > row0) s[j][0] = -1e30f;
                if (col + 1 > row0) s[j][1] = -1e30f;
                if (col     > row1) s[j][2] = -1e30f;
                if (col + 1 > row1) s[j][3] = -1e30f;
            }
            mx0 = fmaxf(mx0, fmaxf(s[j][0], s[j][1]));
            mx1 = fmaxf(mx1, fmaxf(s[j][2], s[j][3]));
        }
        mx0 = fmaxf(mx0, __shfl_xor_sync(0xffffffffu, mx0, 1));
        mx0 = fmaxf(mx0, __shfl_xor_sync(0xffffffffu, mx0, 2));
        mx1 = fmaxf(mx1, __shfl_xor_sync(0xffffffffu, mx1, 1));
        mx1 = fmaxf(mx1, __shfl_xor_sync(0xffffffffu, mx1, 2));

        float mn0 = fmaxf(m_run[0], mx0);
        float mn1 = fmaxf(m_run[1], mx1);
        float cr0 = __expf(m_run[0] - mn0);
        float cr1 = __expf(m_run[1] - mn1);
        m_run[0] = mn0; m_run[1] = mn1;

        float sum0 = 0.f, sum1 = 0.f;
#pragma unroll
        for (int j = 0; j < 16; ++j) {
            s[j][0] = __expf(s[j][0] - mn0);
            s[j][1] = __expf(s[j][1] - mn0);
            s[j][2] = __expf(s[j][2] - mn1);
            s[j][3] = __expf(s[j][3] - mn1);
            sum0 += s[j][0] + s[j][1];
            sum1 += s[j][2] + s[j][3];
        }
        sum0 += __shfl_xor_sync(0xffffffffu, sum0, 1);
        sum0 += __shfl_xor_sync(0xffffffffu, sum0, 2);
        sum1 += __shfl_xor_sync(0xffffffffu, sum1, 1);
        sum1 += __shfl_xor_sync(0xffffffffu, sum1, 2);
        l_run[0] = l_run[0] * cr0 + sum0;
        l_run[1] = l_run[1] * cr1 + sum1;

#pragma unroll
        for (int f = 0; f < 16; ++f) {
            o[f][0] *= cr0; o[f][1] *= cr0;
            o[f][2] *= cr1; o[f][3] *= cr1;
        }

#pragma unroll
        for (int j = 0; j < 16; ++j) {
            *(__half2*)(smh + OFF_PS + (qr + r) * QSH + j * 8 + 2 * c4) =
                __floats2half2_rn(s[j][0], s[j][1]);
            *(__half2*)(smh + OFF_PS + (qr + r + 8) * QSH + j * 8 + 2 * c4) =
                __floats2half2_rn(s[j][2], s[j][3]);
        }
        __syncwarp();

#pragma unroll
        for (int kk = 0; kk < AK; kk += 16) {
            uint32_t a[4];
            ldm_x4(a, ps_a + ((qr + aRow) * QSH + kk + aCol) * 2);
#pragma unroll
            for (int fp = 0; fp < 8; ++fp) {
                uint32_t bb[4];
                ldm_x4(bb, vt_a + ((fp * 16 + bRow) * QSH + kk + bCol) * 2);
                mma_h(o[2 * fp],     a, bb[0], bb[1]);
                mma_h(o[2 * fp + 1], a, bb[2], bb[3]);
            }
        }
    }

    float inv0 = 1.f / l_run[0];
    float inv1 = 1.f / l_run[1];
#pragma unroll
    for (int f = 0; f < 16; ++f) {
        long base0 = (long)row0 * QD + h * HD + f * 8 + 2 * c4;
        *(__half2*)&gctx[base0] =
            __floats2half2_rn(o[f][0] * inv0, o[f][1] * inv0);
        *(__half2*)&gctx[base0 + 8L * QD] =
            __floats2half2_rn(o[f][2] * inv1, o[f][3] * inv1);
    }
}

// ---------------------------------------------------------------------------
extern "C" void kernel_launch(void* const* d_in, const int* in_sizes, int n_in,
                              void* d_out, int out_size) {
    const float* hidden = (const float*)d_in[0];
    const float* Wq = (const float*)d_in[3];
    const float* Wk = (const float*)d_in[4];
    const float* Wv = (const float*)d_in[5];
    const float* Wo = (const float*)d_in[6];
    const float* qw = (const float*)d_in[7];
    const float* kw = (const float*)d_in[8];
    float* out = (float*)d_out;

    __half *phid, *pw1, *pwo, *pqh, *pkh, *pvh, *pvt, *pctx;
    float2* pcs;
    cudaGetSymbolAddress((void**)&phid, g_hid_h);
    cudaGetSymbolAddress((void**)&pw1, g_w1_h);
    cudaGetSymbolAddress((void**)&pwo, g_wo_h);
    cudaGetSymbolAddress((void**)&pqh, g_q_h);
    cudaGetSymbolAddress((void**)&pkh, g_k_h);
    cudaGetSymbolAddress((void**)&pvh, g_v_h);
    cudaGetSymbolAddress((void**)&pvt, g_vt);
    cudaGetSymbolAddress((void**)&pctx, g_ctx_h);
    cudaGetSymbolAddress((void**)&pcs, g_cs);

    cs_table_kernel<<<SEQ, 64>>>(pcs);
    round_all<<<12288, 256>>>(phid, hidden, pw1, Wq, Wk, Wv, pwo, Wo);

    cudaFuncSetAttribute(hgemm, cudaFuncAttributeMaxDynamicSharedMemorySize,
                         GEMM_SMEM_BYTES);

    // Fused QKV projection with norm/rope/V epilogue
    hgemm<<<dim3(N1 / 128, SEQ / 128), 256, GEMM_SMEM_BYTES>>>(
        phid, pw1, nullptr, N1, HIDDEN, 1, pqh, pkh, pvh, qw, kw, pcs);

    vtrans_kernel<<<dim3(SEQ / 32, 1024 / 32), 256>>>(pvh, pvt);

    cudaFuncSetAttribute(attn_mma, cudaFuncAttributeMaxDynamicSharedMemorySize,
                         ATTN_SMEM_BYTES);
    attn_mma<<<dim3(SEQ / AQ, NH), 256, ATTN_SMEM_BYTES>>>(pqh, pkh, pvt, pctx);

    // Output projection -> d_out (plain epilogue)
    hgemm<<<dim3(HIDDEN / 128, SEQ / 128), 256, GEMM_SMEM_BYTES>>>(
        pctx, pwo, out, HIDDEN, HIDDEN, 0, nullptr, nullptr, nullptr,
        nullptr, nullptr, nullptr);
}

// round 12
// speedup vs baseline: 8.7008x; 1.0389x over previous
#include <cuda_runtime.h>
#include <cuda_fp16.h>
#include <math.h>
#include <stdint.h>

#define SEQ 2048
#define HIDDEN 4096
#define NH 32
#define NKV 8
#define HD 128
#define QD (NH*HD)     // 4096
#define N1 6144        // fused Q|K|V output width

// Scratch (static device globals)
__device__ __half g_hid_h[SEQ*HIDDEN];
__device__ __half g_w1_h[N1*HIDDEN];      // [Wq | Wk | Wv] rows
__device__ __half g_wo_h[HIDDEN*QD];
__device__ __half g_q_h[SEQ*QD];          // normed+roped+scaled Q
__device__ __half g_k_h[SEQ*1024];        // normed+roped K
__device__ __half g_vt[1024*SEQ];         // V^T: [kvh*128+d][token]
__device__ __half g_ctx_h[SEQ*QD];
__device__ float2 g_cs[SEQ*64];           // (cos, sin) per (token, freq)

__device__ __forceinline__ void ldm_x4(uint32_t* r, uint32_t addr) {
    asm volatile("ldmatrix.sync.aligned.m8n8.x4.shared.b16 {%0,%1,%2,%3}, [%4];"
        : "=r"(r[0]), "=r"(r[1]), "=r"(r[2]), "=r"(r[3]) : "r"(addr));
}

__device__ __forceinline__ void mma_h(float* d, const uint32_t* a,
                                      uint32_t b0, uint32_t b1) {
    asm volatile(
        "mma.sync.aligned.m16n8k16.row.col.f32.f16.f16.f32 "
        "{%0,%1,%2,%3},{%4,%5,%6,%7},{%8,%9},{%0,%1,%2,%3};\n"
        : "+f"(d[0]), "+f"(d[1]), "+f"(d[2]), "+f"(d[3])
        : "r"(a[0]), "r"(a[1]), "r"(a[2]), "r"(a[3]), "r"(b0), "r"(b1));
}

__device__ __forceinline__ uint32_t packh2(float x, float y) {
    __half2 h = __floats2half2_rn(x, y);
    return *(uint32_t*)&h;
}

// ---------------------------------------------------------------------------
// Merged fp32->fp16 rounding + cos/sin table.
// Blocks 0..12287: 4096-elem rounding ranges (hid 2048 | Wq 4096 | Wk 1024 |
// Wv 1024 | Wo 4096). Blocks 12288..12319: cs table (131072 entries).
// ---------------------------------------------------------------------------
__global__ void __launch_bounds__(256) round_all(
        __half* __restrict__ hid, const float* __restrict__ shid,
        __half* __restrict__ w1,  const float* __restrict__ wq,
        const float* __restrict__ wk, const float* __restrict__ wv,
        __half* __restrict__ wo,  const float* __restrict__ swo,
        float2* __restrict__ cs) {
    long b = blockIdx.x;
    if (b >= 12288) {
        long thr = (b - 12288) * 256 + threadIdx.x;
#pragma unroll
        for (int e = 0; e < 16; ++e) {
            long entry = thr * 16 + e;
            int s = (int)(entry >> 6), f = (int)(entry & 63);
            float invf = exp2f(-19.931568569324174f * ((float)f * (1.0f / 64.0f)));
            float ang = (float)s * invf;
            cs[entry] = make_float2(cosf(ang), sinf(ang));
        }
        return;
    }
    const float* src; __half* dst; long off;
    if (b < 2048)       { src = shid; dst = hid;            off = b; }
    else if (b < 6144)  { src = wq;   dst = w1;             off = b - 2048; }
    else if (b < 7168)  { src = wk;   dst = w1 + 16777216L; off = b - 6144; }
    else if (b < 8192)  { src = wv;   dst = w1 + 20971520L; off = b - 7168; }
    else                { src = swo;  dst = wo;             off = b - 8192; }
    long i = off * 4096 + (long)threadIdx.x * 16;
    float4 v0 = *(const float4*)(src + i);
    float4 v1 = *(const float4*)(src + i + 4);
    float4 v2 = *(const float4*)(src + i + 8);
    float4 v3 = *(const float4*)(src + i + 12);
    __half2 h[8];
    h[0] = __floats2half2_rn(v0.x, v0.y); h[1] = __floats2half2_rn(v0.z, v0.w);
    h[2] = __floats2half2_rn(v1.x, v1.y); h[3] = __floats2half2_rn(v1.z, v1.w);
    h[4] = __floats2half2_rn(v2.x, v2.y); h[5] = __floats2half2_rn(v2.z, v2.w);
    h[6] = __floats2half2_rn(v3.x, v3.y); h[7] = __floats2half2_rn(v3.z, v3.w);
    *(uint4*)(dst + i)     = *(uint4*)h;
    *(uint4*)(dst + i + 8) = *(uint4*)(h + 4);
}

// ---------------------------------------------------------------------------
// fp16 GEMM, 128x128 tile, BK=64, 3-stage cp.async, 2 CTAs/SM.
// mode 0: fp32 C store.  mode 1: fused QKV epilogue:
//   n0 < 4096: Q -> RMSNorm+RoPE+scale -> qh | n0 < 5120: K -> norm+rope -> kh
//   else: V -> transpose in smem -> vt[d][token] fp16
// ---------------------------------------------------------------------------
#define SA_H 72
#define STG_OP_BYTES (128*SA_H*2)
#define STAGE_BYTES (2*STG_OP_BYTES)
#define NST 3
#define GEMM_SMEM_BYTES (NST*STAGE_BYTES)

__global__ void __launch_bounds__(256, 2) hgemm(const __half* __restrict__ A,
                                                const __half* __restrict__ B,
                                                float* __restrict__ C,
                                                int N, int K, int mode,
                                                __half* __restrict__ qh,
                                                __half* __restrict__ kh,
                                                __half* __restrict__ vt,
                                                const float* __restrict__ qw,
                                                const float* __restrict__ kw,
                                                const float2* __restrict__ cs) {
    extern __shared__ char smraw[];
    uint32_t sbase = (uint32_t)__cvta_generic_to_shared(smraw);
    const int tid = threadIdx.x;
    const int lane = tid & 31;
    const int warp = tid >> 5;
    const int wm = (warp & 3) * 32;
    const int wn = (warp >> 2) * 64;
    const int m0 = blockIdx.y * 128, n0 = blockIdx.x * 128;

    float acc[2][8][4];
#pragma unroll
    for (int i = 0; i < 2; ++i)
#pragma unroll
        for (int j = 0; j < 8; ++j)
#pragma unroll
            for (int x = 0; x < 4; ++x) acc[i][j][x] = 0.f;

    const int nk = K >> 6;

    auto prefetch = [&](int t) {
        int slot = t % NST;
        uint32_t sa = sbase + slot * STAGE_BYTES;
        uint32_t sb = sa + STG_OP_BYTES;
        int k0 = t << 6;
#pragma unroll
        for (int i = 0; i < 4; ++i) {
            int c = tid + i * 256;
            int row = c >> 3, cc = c & 7;
            uint32_t da = sa + row * 144 + cc * 16;
            const __half* ga = A + (long)(m0 + row) * K + k0 + cc * 8;
            asm volatile("cp.async.cg.shared.global [%0], [%1], 16;\n" :: "r"(da), "l"(ga));
            uint32_t db = sb + row * 144 + cc * 16;
            const __half* gb = B + (long)(n0 + row) * K + k0 + cc * 8;
            asm volatile("cp.async.cg.shared.global [%0], [%1], 16;\n" :: "r"(db), "l"(gb));
        }
        asm volatile("cp.async.commit_group;\n");
    };

    prefetch(0);
    prefetch(1);

    const int aRow = lane & 15;
    const int aCol = 8 * (lane >> 4);
    const int bRow = (lane & 7) + ((lane >> 4) & 1) * 8;
    const int bCol = ((lane >> 3) & 1) * 8;

    for (int t = 0; t < nk; ++t) {
        asm volatile("cp.async.wait_group 1;\n");
        __syncthreads();
        if (t + 2 < nk) prefetch(t + 2);
        else asm volatile("cp.async.commit_group;\n");

        uint32_t sa = sbase + (t % NST) * STAGE_BYTES;
        uint32_t sb = sa + STG_OP_BYTES;

#pragma unroll
        for (int kk = 0; kk < 64; kk += 16) {
            uint32_t a[2][4];
#pragma unroll
            for (int i = 0; i < 2; ++i)
                ldm_x4(a[i], sa + ((wm + i * 16 + aRow) * SA_H + kk + aCol) * 2);
            uint32_t b[8][2];
#pragma unroll
            for (int jp = 0; jp < 4; ++jp) {
                uint32_t bb[4];
                ldm_x4(bb, sb + ((wn + jp * 16 + bRow) * SA_H + kk + bCol) * 2);
                b[2 * jp][0] = bb[0]; b[2 * jp][1] = bb[1];
                b[2 * jp + 1][0] = bb[2]; b[2 * jp + 1][1] = bb[3];
            }
#pragma unroll
            for (int i = 0; i < 2; ++i)
#pragma unroll
                for (int j = 0; j < 8; ++j)
                    mma_h(acc[i][j], a[i], b[j][0], b[j][1]);
        }
    }

    const int r = lane >> 2, c2 = (lane & 3) * 2;

    if (mode == 0) {
#pragma unroll
        for (int i = 0; i < 2; ++i)
#pragma unroll
            for (int j = 0; j < 8; ++j) {
                long row0 = m0 + wm + i * 16 + r;
                long col = n0 + wn + j * 8 + c2;
                *(float2*)&C[row0 * N + col]       = make_float2(acc[i][j][0], acc[i][j][1]);
                *(float2*)&C[(row0 + 8) * N + col] = make_float2(acc[i][j][2], acc[i][j][3]);
            }
        return;
    }

    if (n0 >= 5120) {
        // V: transpose through smem -> vt[d][token] (coalesced along tokens)
        __half* Smh = (__half*)smraw;     // [128 d][136 token-stride]
        __syncthreads();                   // mainloop smem reads done
#pragma unroll
        for (int i = 0; i < 2; ++i)
#pragma unroll
            for (int j = 0; j < 8; ++j) {
                int tok = wm + i * 16 + r;
                int vd = wn + j * 8 + c2;
                Smh[vd * 136 + tok]           = __float2half_rn(acc[i][j][0]);
                Smh[(vd + 1) * 136 + tok]     = __float2half_rn(acc[i][j][1]);
                Smh[vd * 136 + tok + 8]       = __float2half_rn(acc[i][j][2]);
                Smh[(vd + 1) * 136 + tok + 8] = __float2half_rn(acc[i][j][3]);
            }
        __syncthreads();
        const long dcol0 = n0 - 5120;
#pragma unroll
        for (int u = 0; u < 8; ++u) {
            int idx = tid + u * 256;       // 128 d-rows x 16 uint4 chunks
            int vd = idx >> 4, cc = idx & 15;
            *(uint4*)&vt[(dcol0 + vd) * (long)SEQ + m0 + cc * 8] =
                *(uint4*)&Smh[vd * 136 + cc * 8];
        }
        return;
    }

    // Q or K: RMSNorm over the 128-col head + RoPE
    float* Sm = (float*)smraw;            // [128][132]
    float* part = Sm + 128 * 132;         // [128][2]
    float* rs = part + 256;               // [128]

    __syncthreads();

    float psum[4] = {0.f, 0.f, 0.f, 0.f};
#pragma unroll
    for (int i = 0; i < 2; ++i)
#pragma unroll
        for (int j = 0; j < 8; ++j) {
            int row_a = wm + i * 16 + r;
            int col = wn + j * 8 + c2;
            float a0 = acc[i][j][0], a1 = acc[i][j][1];
            float a2 = acc[i][j][2], a3 = acc[i][j][3];
            *(float2*)&Sm[row_a * 132 + col]       = make_float2(a0, a1);
            *(float2*)&Sm[(row_a + 8) * 132 + col] = make_float2(a2, a3);
            psum[i * 2 + 0] += a0 * a0 + a1 * a1;
            psum[i * 2 + 1] += a2 * a2 + a3 * a3;
        }
#pragma unroll
    for (int k = 0; k < 4; ++k) {
        psum[k] += __shfl_xor_sync(0xffffffffu, psum[k], 1);
        psum[k] += __shfl_xor_sync(0xffffffffu, psum[k], 2);
    }
    if ((lane & 3) == 0) {
        int hfl = warp >> 2;
        part[(wm + r) * 2 + hfl]          = psum[0];
        part[(wm + r + 8) * 2 + hfl]      = psum[1];
        part[(wm + 16 + r) * 2 + hfl]     = psum[2];
        part[(wm + 16 + r + 8) * 2 + hfl] = psum[3];
    }
    __syncthreads();
    if (tid < 128)
        rs[tid] = rsqrtf((part[tid * 2] + part[tid * 2 + 1]) * (1.0f / 128.0f) + 1e-6f);
    __syncthreads();

    const bool isQ = (n0 < 4096);
    const float* w = isQ ? qw : kw;
    __half* dst = isQ ? qh : kh;
    const long dstride = isQ ? 4096 : 1024;
    const long dcol0 = isQ ? n0 : (n0 - 4096);
    const float qs = isQ ? 0.08838834764831845f : 1.0f;

#pragma unroll
    for (int u = 0; u < 32; ++u) {
        int flat = tid + u * 256;
        int row = flat >> 6, cp = flat & 63;
        float rr = rs[row];
        float x1 = Sm[row * 132 + cp]      * rr * w[cp];
        float x2 = Sm[row * 132 + cp + 64] * rr * w[cp + 64];
        float2 csv = cs[(long)(m0 + row) * 64 + cp];
        float y1 = (x1 * csv.x - x2 * csv.y) * qs;
        float y2 = (x2 * csv.x + x1 * csv.y) * qs;
        long base = (long)(m0 + row) * dstride + dcol0;
        dst[base + cp]      = __float2half_rn(y1);
        dst[base + cp + 64] = __float2half_rn(y2);
    }
}

// ---------------------------------------------------------------------------
// Flash attention, fp16 mma. Q tile 128, KV tile 128 (double-buffered).
// Q fragments register-resident; P reused as A-fragment directly (no smem).
// ---------------------------------------------------------------------------
#define AQ 128
#define AK 128
#define QSH 136
#define OFF_QS 0
#define OFF_KS 17408
#define OFF_VT (17408 + 2*17408)
#define ATTN_SMEM_BYTES ((OFF_VT + 2*17408)*2)   // 174080

__global__ void __launch_bounds__(256) attn_mma(const __half* __restrict__ gq,
                                                const __half* __restrict__ gk,
                                                const __half* __restrict__ gvt,
                                                __half* __restrict__ gctx) {
    extern __shared__ __half smh[];
    uint32_t sb = (uint32_t)__cvta_generic_to_shared(smh);
    const uint32_t qs_a = sb + OFF_QS * 2;

    const int tid = threadIdx.x;
    const int lane = tid & 31;
    const int warp = tid >> 5;
    const int r = lane >> 2, c4 = lane & 3;
    const int qblk = gridDim.x - 1 - blockIdx.x;   // heavy blocks first
    const int q0 = qblk * AQ;
    const int h = blockIdx.y;
    const int kvh = h >> 2;
    const int qr = warp * 16;

    const int aRow = lane & 15;
    const int aCol = 8 * (lane >> 4);
    const int bRow = (lane & 7) + ((lane >> 4) & 1) * 8;
    const int bCol = ((lane >> 3) & 1) * 8;

    const int ntiles = qblk + 1;

    auto fill = [&](int t) {
        int slot = t & 1;
        int k0 = t * AK;
        uint32_t ka = sb + (OFF_KS + slot * 17408) * 2;
        uint32_t va = sb + (OFF_VT + slot * 17408) * 2;
#pragma unroll
        for (int i = 0; i < 8; ++i) {
            int idx = tid + i * 256;
            int row = idx >> 4, cc = idx & 15;
            uint32_t dst = ka + row * 272 + cc * 16;
            const __half* src = gk + (long)(k0 + row) * 1024 + kvh * HD + cc * 8;
            asm volatile("cp.async.cg.shared.global [%0], [%1], 16;\n" :: "r"(dst), "l"(src));
        }
#pragma unroll
        for (int i = 0; i < 8; ++i) {
            int idx = tid + i * 256;
            int row = idx >> 4, cc = idx & 15;
            uint32_t dst = va + row * 272 + cc * 16;
            const __half* src = gvt + (long)(kvh * HD + row) * SEQ + k0 + cc * 8;
            asm volatile("cp.async.cg.shared.global [%0], [%1], 16;\n" :: "r"(dst), "l"(src));
        }
        asm volatile("cp.async.commit_group;\n");
    };

    fill(0);

    // Q tile -> smem -> register fragments (invariant across KV tiles)
#pragma unroll
    for (int i = 0; i < 8; ++i) {
        int idx = tid + i * 256;
        int row = idx >> 4, cc = idx & 15;
        *(uint4*)(smh + OFF_QS + row * QSH + cc * 8) =
            *(const uint4*)(gq + (long)(q0 + row) * QD + h * HD + cc * 8);
    }
    __syncthreads();
    uint32_t qf[8][4];
#pragma unroll
    for (int kk = 0; kk < 8; ++kk)
        ldm_x4(qf[kk], qs_a + ((qr + aRow) * QSH + kk * 16 + aCol) * 2);

    float m_run[2] = {-1e30f, -1e30f};
    float l_run[2] = {0.f, 0.f};
    float o[16][4];
#pragma unroll
    for (int f = 0; f < 16; ++f)
#pragma unroll
        for (int x = 0; x < 4; ++x) o[f][x] = 0.f;

    const int row0 = q0 + qr + r;
    const int row1 = row0 + 8;

    for (int t = 0; t < ntiles; ++t) {
        const int k0 = t * AK;
        __syncthreads();                   // prev readers of refill slot done
        if (t + 1 < ntiles) {
            fill(t + 1);
            asm volatile("cp.async.wait_group 1;\n");
        } else {
            asm volatile("cp.async.wait_group 0;\n");
        }
        __syncthreads();                   // tile t visible

        const uint32_t ks_a = sb + (OFF_KS + (t & 1) * 17408) * 2;
        const uint32_t vt_a = sb + (OFF_VT + (t & 1) * 17408) * 2;

        // S = Q K^T : 16x128 per warp (Q from registers)
        float s[16][4];
#pragma unroll
        for (int j = 0; j < 16; ++j)
#pragma unroll
            for (int x = 0; x < 4; ++x) s[j][x] = 0.f;

#pragma unroll
        for (int kk = 0; kk < 8; ++kk) {
#pragma unroll
            for (int jp = 0; jp < 8; ++jp) {
                uint32_t bb[4];
                ldm_x4(bb, ks_a + ((jp * 16 + bRow) * QSH + kk * 16 + bCol) * 2);
                mma_h(s[2 * jp],     qf[kk], bb[0], bb[1]);
                mma_h(s[2 * jp + 1], qf[kk], bb[2], bb[3]);
            }
        }

        // online softmax (mask only diagonal tile)
        const bool dg = (t == ntiles - 1);
        float mx0 = -1e30f, mx1 = -1e30f;
#pragma unroll
        for (int j = 0; j < 16; ++j) {
            int col = k0 + j * 8 + 2 * c4;
            if (dg) {
                if (col     > row0) s[j][0] = -1e30f;
                if (col + 1 > row0) s[j][1] = -1e30f;
                if (col     > row1) s[j][2] = -1e30f;
                if (col + 1 > row1) s[j][3] = -1e30f;
            }
            mx0 = fmaxf(mx0, fmaxf(s[j][0], s[j][1]));
            mx1 = fmaxf(mx1, fmaxf(s[j][2], s[j][3]));
        }
        mx0 = fmaxf(mx0, __shfl_xor_sync(0xffffffffu, mx0, 1));
        mx0 = fmaxf(mx0, __shfl_xor_sync(0xffffffffu, mx0, 2));
        mx1 = fmaxf(mx1, __shfl_xor_sync(0xffffffffu, mx1, 1));
        mx1 = fmaxf(mx1, __shfl_xor_sync(0xffffffffu, mx1, 2));

        float mn0 = fmaxf(m_run[0], mx0);
        float mn1 = fmaxf(m_run[1], mx1);
        float cr0 = __expf(m_run[0] - mn0);
        float cr1 = __expf(m_run[1] - mn1);
        m_run[0] = mn0; m_run[1] = mn1;

        float sum0 = 0.f, sum1 = 0.f;
#pragma unroll
        for (int j = 0; j < 16; ++j) {
            s[j][0] = __expf(s[j][0] - mn0);
            s[j][1] = __expf(s[j][1] - mn0);
            s[j][2] = __expf(s[j][2] - mn1);
            s[j][3] = __expf(s[j][3] - mn1);
            sum0 += s[j][0] + s[j][1];
            sum1 += s[j][2] + s[j][3];
        }
        sum0 += __shfl_xor_sync(0xffffffffu, sum0, 1);
        sum0 += __shfl_xor_sync(0xffffffffu, sum0, 2);
        sum1 += __shfl_xor_sync(0xffffffffu, sum1, 1);
        sum1 += __shfl_xor_sync(0xffffffffu, sum1, 2);
        l_run[0] = l_run[0] * cr0 + sum0;
        l_run[1] = l_run[1] * cr1 + sum1;

#pragma unroll
        for (int f = 0; f < 16; ++f) {
            o[f][0] *= cr0; o[f][1] *= cr0;
            o[f][2] *= cr1; o[f][3] *= cr1;
        }

        // O += P V : P packed directly from S fragments (no smem round-trip)
#pragma unroll
        for (int kt = 0; kt < 8; ++kt) {
            uint32_t a[4];
            a[0] = packh2(s[2 * kt][0],     s[2 * kt][1]);
            a[1] = packh2(s[2 * kt][2],     s[2 * kt][3]);
            a[2] = packh2(s[2 * kt + 1][0], s[2 * kt + 1][1]);
            a[3] = packh2(s[2 * kt + 1][2], s[2 * kt + 1][3]);
#pragma unroll
            for (int fp = 0; fp < 8; ++fp) {
                uint32_t bb[4];
                ldm_x4(bb, vt_a + ((fp * 16 + bRow) * QSH + kt * 16 + bCol) * 2);
                mma_h(o[2 * fp],     a, bb[0], bb[1]);
                mma_h(o[2 * fp + 1], a, bb[2], bb[3]);
            }
        }
    }

    float inv0 = 1.f / l_run[0];
    float inv1 = 1.f / l_run[1];
#pragma unroll
    for (int f = 0; f < 16; ++f) {
        long base0 = (long)row0 * QD + h * HD + f * 8 + 2 * c4;
        *(__half2*)&gctx[base0] =
            __floats2half2_rn(o[f][0] * inv0, o[f][1] * inv0);
        *(__half2*)&gctx[base0 + 8L * QD] =
            __floats2half2_rn(o[f][2] * inv1, o[f][3] * inv1);
    }
}

// ---------------------------------------------------------------------------
extern "C" void kernel_launch(void* const* d_in, const int* in_sizes, int n_in,
                              void* d_out, int out_size) {
    const float* hidden = (const float*)d_in[0];
    const float* Wq = (const float*)d_in[3];
    const float* Wk = (const float*)d_in[4];
    const float* Wv = (const float*)d_in[5];
    const float* Wo = (const float*)d_in[6];
    const float* qw = (const float*)d_in[7];
    const float* kw = (const float*)d_in[8];
    float* out = (float*)d_out;

    __half *phid, *pw1, *pwo, *pqh, *pkh, *pvt, *pctx;
    float2* pcs;
    cudaGetSymbolAddress((void**)&phid, g_hid_h);
    cudaGetSymbolAddress((void**)&pw1, g_w1_h);
    cudaGetSymbolAddress((void**)&pwo, g_wo_h);
    cudaGetSymbolAddress((void**)&pqh, g_q_h);
    cudaGetSymbolAddress((void**)&pkh, g_k_h);
    cudaGetSymbolAddress((void**)&pvt, g_vt);
    cudaGetSymbolAddress((void**)&pctx, g_ctx_h);
    cudaGetSymbolAddress((void**)&pcs, g_cs);

    // Rounding + cs table, one launch
    round_all<<<12320, 256>>>(phid, hidden, pw1, Wq, Wk, Wv, pwo, Wo, pcs);

    cudaFuncSetAttribute(hgemm, cudaFuncAttributeMaxDynamicSharedMemorySize,
                         GEMM_SMEM_BYTES);

    // Fused QKV projection with norm/rope/V-transpose epilogue
    hgemm<<<dim3(N1 / 128, SEQ / 128), 256, GEMM_SMEM_BYTES>>>(
        phid, pw1, nullptr, N1, HIDDEN, 1, pqh, pkh, pvt, qw, kw, pcs);

    cudaFuncSetAttribute(attn_mma, cudaFuncAttributeMaxDynamicSharedMemorySize,
                         ATTN_SMEM_BYTES);
    attn_mma<<<dim3(SEQ / AQ, NH), 256, ATTN_SMEM_BYTES>>>(pqh, pkh, pvt, pctx);

    // Output projection -> d_out
    hgemm<<<dim3(HIDDEN / 128, SEQ / 128), 256, GEMM_SMEM_BYTES>>>(
        pctx, pwo, out, HIDDEN, HIDDEN, 0, nullptr, nullptr, nullptr,
        nullptr, nullptr, nullptr);
}